// round 4
// baseline (speedup 1.0000x reference)
#include <cuda_runtime.h>
#include <cuda_bf16.h>
#include <math.h>

// Problem constants
#define Bsz 4096
#define Ssz 1536
#define Lsz 2048
#define Hsz 1024
#define MINTOK 460                     // int(0.3*1536)
#define NEEDFIX_THRESH (Ssz - MINTOK)  // 1076

// ---------------- scratch (device globals; no allocations allowed) ----------
__device__ float g_A [(size_t)Bsz * Lsz];
__device__ float g_Bf[(size_t)Bsz * Lsz];
__device__ float g_C1[(size_t)Bsz * Hsz];
__device__ float g_C2[(size_t)Bsz * Hsz];
__device__ float g_C3[(size_t)Bsz * Hsz];
__device__ float g_D1[(size_t)Bsz * (Hsz/2)];
__device__ float g_D2[(size_t)Bsz * (Hsz/4)];

#define CCH 16
__device__ double g_p1[CCH * Lsz];
__device__ double g_p2[CCH * Lsz];
__device__ double g_p3[CCH * Lsz];
__device__ double g_S1[Lsz], g_S2[Lsz], g_S3[Lsz];
__device__ float  g_adj[Lsz];
__device__ float  g_rowEnt[Bsz], g_rowDiff[Bsz];
__device__ double g_cons[1];

// ---------------- GEMM: C[M,N] = A[M,K] @ W[N,K]^T + bias[N] ----------------
// Numerics contract (do not change): fp32 FFMA over each ascending 16-k chunk
// per output, folded into a double accumulator per output, chunks ascending.
// Perf: 128x64 tile, 8x4/thread, 256 threads, 2 CTAs/SM, double-buffered smem
// with register prefetch of the next chunk.
__global__ void __launch_bounds__(256, 2)
sgemm_nt(const float* __restrict__ A, const float* __restrict__ W,
         const float* __restrict__ bias, float* __restrict__ C,
         int M, int N, int K)
{
    constexpr int BK = 16;
    __shared__ float As[2][BK][128 + 4];
    __shared__ float Bs[2][BK][64 + 4];
    const int tid = threadIdx.x;
    const int bm = blockIdx.y * 128;
    const int bn = blockIdx.x * 64;
    const int tr = (tid >> 4) << 3;     // 0..120 step 8
    const int tc = (tid & 15) << 2;     // 0..60 step 4

    const int arow = tid & 127;         // A row within tile
    const int ak   = (tid >> 7) << 3;   // 0 or 8 (k offset)
    const int brow = tid & 63;          // B row within tile
    const int bk   = (tid >> 6) << 2;   // 0,4,8,12 (k offset)

    const float* Ap = A + (size_t)(bm + arow) * K + ak;
    const float* Wp = W + (size_t)(bn + brow) * K + bk;

    double dacc[8][4];
#pragma unroll
    for (int i = 0; i < 8; i++)
#pragma unroll
        for (int j = 0; j < 4; j++) dacc[i][j] = 0.0;

    const int nch = K / BK;

    // prologue: stage chunk 0
    float4 a0 = *(const float4*)(Ap);
    float4 a1 = *(const float4*)(Ap + 4);
    float4 bq = *(const float4*)(Wp);
    As[0][ak + 0][arow] = a0.x; As[0][ak + 1][arow] = a0.y;
    As[0][ak + 2][arow] = a0.z; As[0][ak + 3][arow] = a0.w;
    As[0][ak + 4][arow] = a1.x; As[0][ak + 5][arow] = a1.y;
    As[0][ak + 6][arow] = a1.z; As[0][ak + 7][arow] = a1.w;
    Bs[0][bk + 0][brow] = bq.x; Bs[0][bk + 1][brow] = bq.y;
    Bs[0][bk + 2][brow] = bq.z; Bs[0][bk + 3][brow] = bq.w;
    __syncthreads();

    for (int c = 0; c < nch; c++) {
        const int buf = c & 1;
        const bool more = (c + 1 < nch);
        if (more) {
            const int k0 = (c + 1) * BK;
            a0 = *(const float4*)(Ap + k0);
            a1 = *(const float4*)(Ap + k0 + 4);
            bq = *(const float4*)(Wp + k0);
        }

        float facc[8][4];
#pragma unroll
        for (int i = 0; i < 8; i++)
#pragma unroll
            for (int j = 0; j < 4; j++) facc[i][j] = 0.f;

#pragma unroll
        for (int k = 0; k < BK; k++) {
            float a[8], b[4];
            *(float4*)(b)     = *(const float4*)(&Bs[buf][k][tc]);
            *(float4*)(a)     = *(const float4*)(&As[buf][k][tr]);
            *(float4*)(a + 4) = *(const float4*)(&As[buf][k][tr + 4]);
#pragma unroll
            for (int i = 0; i < 8; i++)
#pragma unroll
                for (int j = 0; j < 4; j++)
                    facc[i][j] = fmaf(a[i], b[j], facc[i][j]);
        }
#pragma unroll
        for (int i = 0; i < 8; i++)
#pragma unroll
            for (int j = 0; j < 4; j++) dacc[i][j] += (double)facc[i][j];

        if (more) {
            __syncthreads();
            const int nb = buf ^ 1;
            As[nb][ak + 0][arow] = a0.x; As[nb][ak + 1][arow] = a0.y;
            As[nb][ak + 2][arow] = a0.z; As[nb][ak + 3][arow] = a0.w;
            As[nb][ak + 4][arow] = a1.x; As[nb][ak + 5][arow] = a1.y;
            As[nb][ak + 6][arow] = a1.z; As[nb][ak + 7][arow] = a1.w;
            Bs[nb][bk + 0][brow] = bq.x; Bs[nb][bk + 1][brow] = bq.y;
            Bs[nb][bk + 2][brow] = bq.z; Bs[nb][bk + 3][brow] = bq.w;
            __syncthreads();
        }
    }

    float bj[4];
#pragma unroll
    for (int j = 0; j < 4; j++) bj[j] = bias[bn + tc + j];
#pragma unroll
    for (int i = 0; i < 8; i++) {
        float* Cp = C + (size_t)(bm + tr + i) * N + bn + tc;
        float4 v = make_float4(__fadd_rn((float)dacc[i][0], bj[0]),
                               __fadd_rn((float)dacc[i][1], bj[1]),
                               __fadd_rn((float)dacc[i][2], bj[2]),
                               __fadd_rn((float)dacc[i][3], bj[3]));
        *(float4*)Cp = v;
    }
}

// ---------------- LN of padded int input -> X0 (double-precise stats) -------
__global__ void ln_input_kernel(const int* __restrict__ ids,
                                const float* __restrict__ gam,
                                const float* __restrict__ bet,
                                float* __restrict__ out)
{
    __shared__ float s[Lsz];
    __shared__ double red[256];
    const int r = blockIdx.x, tid = threadIdx.x;
    for (int j = tid; j < Lsz; j += 256)
        s[j] = (j < Ssz) ? (float)ids[(size_t)r * Ssz + j] : 0.f;
    __syncthreads();
    double p = 0.0;
    for (int j = tid; j < Lsz; j += 256) p += (double)s[j];
    red[tid] = p; __syncthreads();
    for (int o = 128; o > 0; o >>= 1) { if (tid < o) red[tid] += red[tid + o]; __syncthreads(); }
    const double mean = red[0] / (double)Lsz;
    const float  mf   = (float)mean;
    __syncthreads();
    double v = 0.0;
    for (int j = tid; j < Lsz; j += 256) { double d = (double)s[j] - mean; v += d * d; }
    red[tid] = v; __syncthreads();
    for (int o = 128; o > 0; o >>= 1) { if (tid < o) red[tid] += red[tid + o]; __syncthreads(); }
    const float vf  = (float)(red[0] / (double)Lsz);
    const float arg = __fadd_rn(vf, 1e-5f);
    const float rs  = (float)(1.0 / sqrt((double)arg));
    for (int j = tid; j < Lsz; j += 256) {
        float t = __fmul_rn(__fmul_rn(__fsub_rn(s[j], mf), rs), gam[j]);
        out[(size_t)r * Lsz + j] = __fadd_rn(t, bet[j]);
    }
}

// ---------------- LN + exact GELU (+ optional residual), per row ------------
__global__ void ln_gelu_kernel(const float* __restrict__ in,
                               const float* __restrict__ gam,
                               const float* __restrict__ bet,
                               const float* __restrict__ res,
                               float* __restrict__ out, int n)
{
    __shared__ float s[Lsz];
    __shared__ double red[256];
    const int r = blockIdx.x, tid = threadIdx.x;
    for (int j = tid; j < n; j += 256) s[j] = in[(size_t)r * n + j];
    __syncthreads();
    double p = 0.0;
    for (int j = tid; j < n; j += 256) p += (double)s[j];
    red[tid] = p; __syncthreads();
    for (int o = 128; o > 0; o >>= 1) { if (tid < o) red[tid] += red[tid + o]; __syncthreads(); }
    const double mean = red[0] / (double)n;
    const float  mf   = (float)mean;
    __syncthreads();
    double v = 0.0;
    for (int j = tid; j < n; j += 256) { double d = (double)s[j] - mean; v += d * d; }
    red[tid] = v; __syncthreads();
    for (int o = 128; o > 0; o >>= 1) { if (tid < o) red[tid] += red[tid + o]; __syncthreads(); }
    const float vf  = (float)(red[0] / (double)n);
    const float arg = __fadd_rn(vf, 1e-5f);
    const float rs  = (float)(1.0 / sqrt((double)arg));
    for (int j = tid; j < n; j += 256) {
        float x = __fadd_rn(__fmul_rn(__fmul_rn(__fsub_rn(s[j], mf), rs), gam[j]), bet[j]);
        double u = (double)x * 0.7071067811865475244;
        float e = (float)erf(u);
        float ge = __fmul_rn(__fmul_rn(x, __fadd_rn(e, 1.f)), 0.5f);
        float o = res ? __fadd_rn(ge, res[(size_t)r * n + j]) : ge;
        out[(size_t)r * n + j] = o;
    }
}

// ---------------- mu -> z = sigmoid(clip(mu,-5,5)), exact -------------------
__global__ void sigmoid_kernel(const float* __restrict__ mu, float* __restrict__ z)
{
    size_t i = (size_t)blockIdx.x * 256 + threadIdx.x;
    if (i < (size_t)Bsz * Lsz) {
        float m = mu[i];
        m = fminf(5.f, fmaxf(-5.f, m));
        z[i] = (float)(1.0 / (1.0 + exp(-(double)m)));
    }
}

// ---------------- column stats ----------------------------------------------
__global__ void colstats_kernel(const float* __restrict__ Z)
{
    const int j  = blockIdx.x * 256 + threadIdx.x;
    const int ch = blockIdx.y;
    const int r0 = ch * (Bsz / CCH);
    const bool hasN = (j < Lsz - 1);
    double s1 = 0, s2 = 0, s3 = 0;
    for (int r = r0; r < r0 + (Bsz / CCH); ++r) {
        float z  = Z[(size_t)r * Lsz + j];
        float zn = hasN ? Z[(size_t)r * Lsz + j + 1] : 0.f;
        s1 += (double)z;
        s2 += (double)z * (double)z;
        s3 += (double)z * (double)zn;
    }
    g_p1[ch * Lsz + j] = s1;
    g_p2[ch * Lsz + j] = s2;
    g_p3[ch * Lsz + j] = s3;
}

__global__ void colcombine_kernel()
{
    const int j = blockIdx.x * 256 + threadIdx.x;
    double s1 = 0, s2 = 0, s3 = 0;
    for (int c = 0; c < CCH; c++) {
        s1 += g_p1[c * Lsz + j];
        s2 += g_p2[c * Lsz + j];
        s3 += g_p3[c * Lsz + j];
    }
    g_S1[j] = s1; g_S2[j] = s2; g_S3[j] = s3;
}

// ---------------- adj (corr>0.5) + consistency term -------------------------
__global__ void adjcons_kernel(const float* __restrict__ fe)
{
    __shared__ double red[256];
    const int tid = threadIdx.x;
    double cons = 0.0;
    for (int j = tid; j < Lsz; j += 256) {
        double m = g_S1[j] / (double)Bsz;
        cons += fabs(m - (double)fe[j]);
        if (j < Lsz - 1) {
            double cov = g_S3[j] - g_S1[j] * g_S1[j + 1] / (double)Bsz;
            double v1  = g_S2[j]     - g_S1[j]     * g_S1[j]     / (double)Bsz;
            double v2  = g_S2[j + 1] - g_S1[j + 1] * g_S1[j + 1] / (double)Bsz;
            double den = v1 * v2;
            float a = 0.f;
            if (den > 0.0 && cov / sqrt(den) > 0.5) a = 1.f;
            g_adj[j] = a;
        }
    }
    red[tid] = cons; __syncthreads();
    for (int o = 128; o > 0; o >>= 1) { if (tid < o) red[tid] += red[tid + o]; __syncthreads(); }
    if (tid == 0) g_cons[0] = red[0];
}

// ---------------- per-row mask / top-k / outputs -----------------------------
__global__ void __launch_bounds__(256)
rowmask_kernel(const float* __restrict__ Z, const int* __restrict__ ids,
               float* __restrict__ outG, float* __restrict__ outZ)
{
    __shared__ float zs[Lsz];
    __shared__ float redf[256];
    __shared__ int   redi[256];
    __shared__ unsigned int hist[256];
    __shared__ unsigned int sh_prefix;
    __shared__ int sh_k;
    __shared__ int wsum[8];

    const int r = blockIdx.x, tid = threadIdx.x;
    for (int j = tid; j < Lsz; j += 256) zs[j] = Z[(size_t)r * Lsz + j];
    __syncthreads();

    float ent = 0.f, dif = 0.f;
    int cnt = 0;
    for (int j = tid; j < Lsz; j += 256) {
        float p = zs[j];
        ent += -(p * logf(__fadd_rn(p, 1e-7f)) +
                 (1.f - p) * logf(__fadd_rn(__fsub_rn(1.f, p), 1e-7f)));
        if (j < Lsz - 1) dif += fabsf(__fsub_rn(zs[j + 1], zs[j])) * g_adj[j];
        if (j < Ssz) {
            int tok = ids[(size_t)r * Ssz + j];
            if (p < 0.5f && tok != 0) cnt++;
        }
    }
    redf[tid] = ent; __syncthreads();
    for (int o = 128; o > 0; o >>= 1) { if (tid < o) redf[tid] += redf[tid + o]; __syncthreads(); }
    if (tid == 0) g_rowEnt[r] = redf[0];
    __syncthreads();
    redf[tid] = dif; __syncthreads();
    for (int o = 128; o > 0; o >>= 1) { if (tid < o) redf[tid] += redf[tid + o]; __syncthreads(); }
    if (tid == 0) g_rowDiff[r] = redf[0];
    __syncthreads();
    redi[tid] = cnt; __syncthreads();
    for (int o = 128; o > 0; o >>= 1) { if (tid < o) redi[tid] += redi[tid + o]; __syncthreads(); }
    const int total = redi[0];
    __syncthreads();
    const bool needfix = total > NEEDFIX_THRESH;

    unsigned int tsel = 0;
    int nEqKeep = 0;
    if (needfix) {
        unsigned int prefix = 0, highmask = 0;
        int k = MINTOK;
        for (int pass = 0; pass < 4; pass++) {
            const int shift = 24 - 8 * pass;
            hist[tid] = 0;
            __syncthreads();
            for (int j = tid; j < Ssz; j += 256) {
                unsigned int key = __float_as_uint(zs[j]);
                if ((key & highmask) == prefix)
                    atomicAdd(&hist[(key >> shift) & 0xFFu], 1u);
            }
            __syncthreads();
            if (tid == 0) {
                int cum = 0, b = 255;
                for (; b >= 0; --b) { cum += (int)hist[b]; if (cum >= k) break; }
                sh_k = k - (cum - (int)hist[b]);
                sh_prefix = prefix | ((unsigned int)b << shift);
            }
            __syncthreads();
            prefix = sh_prefix;
            k = sh_k;
            highmask |= 0xFFu << shift;
            __syncthreads();
        }
        tsel = prefix;
        int cg = 0;
        for (int j = tid; j < Ssz; j += 256)
            if (__float_as_uint(zs[j]) > tsel) cg++;
        redi[tid] = cg; __syncthreads();
        for (int o = 128; o > 0; o >>= 1) { if (tid < o) redi[tid] += redi[tid + o]; __syncthreads(); }
        nEqKeep = MINTOK - redi[0];
        __syncthreads();
    }

    int runEq = 0;
    for (int base = 0; base < Ssz; base += 256) {
        const int j = base + tid;
        const float zv = zs[j];
        const int tok = ids[(size_t)r * Ssz + j];
        bool m = (zv < 0.5f) && (tok != 0);
        if (needfix) {
            const unsigned int key = __float_as_uint(zv);
            const int eq = (key == tsel) ? 1 : 0;
            const unsigned int bal = __ballot_sync(0xffffffffu, eq);
            const int lane = tid & 31, w = tid >> 5;
            const int wexcl = __popc(bal & ((1u << lane) - 1u));
            if (lane == 31) wsum[w] = __popc(bal);
            __syncthreads();
            int woff = 0;
            for (int i = 0; i < w; i++) woff += wsum[i];
            const int excl = woff + wexcl;
            const bool keep = (key > tsel) || (eq && (runEq + excl) < nEqKeep);
            if (keep) m = false;
            __syncthreads();
            if (tid == 0) { int t = 0; for (int i = 0; i < 8; i++) t += wsum[i]; redi[0] = t; }
            __syncthreads();
            runEq += redi[0];
        }
        if (j == 0) m = false;
        outG[(size_t)r * Ssz + j] = m ? 0.f : (float)tok;
        outZ[(size_t)r * Ssz + j] = zv;
    }
}

// ---------------- final loss scalar -----------------------------------------
__global__ void finalize_kernel(float* __restrict__ out)
{
    __shared__ double red[256];
    const int tid = threadIdx.x;
    double e = 0, d = 0;
    for (int r = tid; r < Bsz; r += 256) {
        e += (double)g_rowEnt[r];
        d += (double)g_rowDiff[r];
    }
    red[tid] = e; __syncthreads();
    for (int o = 128; o > 0; o >>= 1) { if (tid < o) red[tid] += red[tid + o]; __syncthreads(); }
    const double entSum = red[0];
    __syncthreads();
    red[tid] = d; __syncthreads();
    for (int o = 128; o > 0; o >>= 1) { if (tid < o) red[tid] += red[tid + o]; __syncthreads(); }
    const double difSum = red[0];
    if (tid == 0) {
        double R1 = -0.001 * entSum / ((double)Bsz * (double)Lsz);
        double R2 =  0.001 * difSum / ((double)Bsz * (double)(Lsz - 1));
        double cons = 0.001 * g_cons[0] / (double)Lsz;
        out[(size_t)Bsz * Ssz] = (float)(R1 + R2 + cons);
    }
}

// ---------------- launch ------------------------------------------------------
extern "C" void kernel_launch(void* const* d_in, const int* in_sizes, int n_in,
                              void* d_out, int out_size)
{
    const float* in_g  = (const float*)d_in[0];
    const float* in_b  = (const float*)d_in[1];
    const float* wv    = (const float*)d_in[2];
    const float* bv    = (const float*)d_in[3];
    const float* wo    = (const float*)d_in[4];
    const float* bo    = (const float*)d_in[5];
    const float* w2    = (const float*)d_in[6];
    const float* b2    = (const float*)d_in[7];
    const float* g1    = (const float*)d_in[8];
    const float* be1   = (const float*)d_in[9];
    const float* w4    = (const float*)d_in[10];
    const float* b4    = (const float*)d_in[11];
    const float* g3    = (const float*)d_in[12];
    const float* be3   = (const float*)d_in[13];
    const float* w5    = (const float*)d_in[14];
    const float* b5    = (const float*)d_in[15];
    const float* g4    = (const float*)d_in[16];
    const float* be4   = (const float*)d_in[17];
    const float* w6    = (const float*)d_in[18];
    const float* b6    = (const float*)d_in[19];
    const float* g5    = (const float*)d_in[20];
    const float* be5   = (const float*)d_in[21];
    const float* w7    = (const float*)d_in[22];
    const float* b7    = (const float*)d_in[23];
    const float* g6    = (const float*)d_in[24];
    const float* be6   = (const float*)d_in[25];
    const float* wout  = (const float*)d_in[26];
    const float* bout  = (const float*)d_in[27];
    const float* fe    = (const float*)d_in[28];
    const int*   ids   = (const int*)d_in[29];
    float* out = (float*)d_out;

    float *pA, *pBf, *pC1, *pC2, *pC3, *pD1, *pD2;
    cudaGetSymbolAddress((void**)&pA,  g_A);
    cudaGetSymbolAddress((void**)&pBf, g_Bf);
    cudaGetSymbolAddress((void**)&pC1, g_C1);
    cudaGetSymbolAddress((void**)&pC2, g_C2);
    cudaGetSymbolAddress((void**)&pC3, g_C3);
    cudaGetSymbolAddress((void**)&pD1, g_D1);
    cudaGetSymbolAddress((void**)&pD2, g_D2);

    ln_input_kernel<<<Bsz, 256>>>(ids, in_g, in_b, pA);

    sgemm_nt<<<dim3(Lsz/64, Bsz/128), 256>>>(pA,  wv, bv, pBf, Bsz, Lsz, Lsz);
    sgemm_nt<<<dim3(Lsz/64, Bsz/128), 256>>>(pBf, wo, bo, pA,  Bsz, Lsz, Lsz);

    sgemm_nt<<<dim3(Hsz/64, Bsz/128), 256>>>(pA, w2, b2, pC1, Bsz, Hsz, Lsz);
    ln_gelu_kernel<<<Bsz, 256>>>(pC1, g1, be1, pC1, pC2, Hsz);

    sgemm_nt<<<dim3(Hsz/64, Bsz/128), 256>>>(pC2, w4, b4, pC3, Bsz, Hsz, Hsz);
    ln_gelu_kernel<<<Bsz, 256>>>(pC3, g3, be3, nullptr, pC3, Hsz);

    sgemm_nt<<<dim3(Hsz/64, Bsz/128), 256>>>(pC3, w5, b5, pC1, Bsz, Hsz, Hsz);
    ln_gelu_kernel<<<Bsz, 256>>>(pC1, g4, be4, pC2, pC1, Hsz);

    sgemm_nt<<<dim3((Hsz/2)/64, Bsz/128), 256>>>(pC1, w6, b6, pD1, Bsz, Hsz/2, Hsz);
    ln_gelu_kernel<<<Bsz, 256>>>(pD1, g5, be5, nullptr, pD1, Hsz/2);

    sgemm_nt<<<dim3((Hsz/4)/64, Bsz/128), 256>>>(pD1, w7, b7, pD2, Bsz, Hsz/4, Hsz/2);
    ln_gelu_kernel<<<Bsz, 256>>>(pD2, g6, be6, nullptr, pD2, Hsz/4);

    sgemm_nt<<<dim3(Lsz/64, Bsz/128), 256>>>(pD2, wout, bout, pBf, Bsz, Lsz, Hsz/4);
    sigmoid_kernel<<<(Bsz*Lsz)/256, 256>>>(pBf, pA);

    colstats_kernel<<<dim3(Lsz/256, CCH), 256>>>(pA);
    colcombine_kernel<<<Lsz/256, 256>>>();
    adjcons_kernel<<<1, 256>>>(fe);

    rowmask_kernel<<<Bsz, 256>>>(pA, ids, out, out + (size_t)Bsz * Ssz + 1);

    finalize_kernel<<<1, 256>>>(out);
}

// round 5
// speedup vs baseline: 1.7035x; 1.7035x over previous
#include <cuda_runtime.h>
#include <cuda_bf16.h>
#include <math.h>

// Problem constants
#define Bsz 4096
#define Ssz 1536
#define Lsz 2048
#define Hsz 1024
#define MINTOK 460                     // int(0.3*1536)
#define NEEDFIX_THRESH (Ssz - MINTOK)  // 1076

// ---------------- scratch (device globals; no allocations allowed) ----------
__device__ float g_A [(size_t)Bsz * Lsz];
__device__ float g_Bf[(size_t)Bsz * Lsz];
__device__ float g_C1[(size_t)Bsz * Hsz];
__device__ float g_C2[(size_t)Bsz * Hsz];
__device__ float g_C3[(size_t)Bsz * Hsz];
__device__ float g_D1[(size_t)Bsz * (Hsz/2)];
__device__ float g_D2[(size_t)Bsz * (Hsz/4)];

#define CCH 16
__device__ double g_p1[CCH * Lsz];
__device__ double g_p2[CCH * Lsz];
__device__ double g_p3[CCH * Lsz];
__device__ double g_S1[Lsz], g_S2[Lsz], g_S3[Lsz];
__device__ float  g_adj[Lsz];
__device__ float  g_rowEnt[Bsz], g_rowDiff[Bsz];
__device__ double g_cons[1];

// ---------------- GEMM: C[M,N] = A[M,K] @ W[N,K]^T + bias[N] ----------------
// Numerics contract (do not change): per output, fp32 FFMA over each ascending
// 16-k chunk, folded ascending into a double accumulator, all by one thread.
// Bitwise identical to the round-3 passing kernel.
// Perf: 64x64 tile, 4x4/thread, 256 threads, ~110 regs -> 2 CTAs/SM natural,
// double-buffered smem + register prefetch.
__global__ void __launch_bounds__(256)
sgemm_nt(const float* __restrict__ A, const float* __restrict__ W,
         const float* __restrict__ bias, float* __restrict__ C,
         int M, int N, int K)
{
    constexpr int BK = 16;
    __shared__ float As[2][BK][64 + 4];
    __shared__ float Bs[2][BK][64 + 4];
    const int tid = threadIdx.x;
    const int bm = blockIdx.y * 64;
    const int bn = blockIdx.x * 64;
    const int tr = (tid >> 4) << 2;     // 0..60 step 4 (C row offset)
    const int tc = (tid & 15) << 2;     // 0..60 step 4 (C col offset)

    const int lrow = tid & 63;          // tile row for loads
    const int lk   = (tid >> 6) << 2;   // 0,4,8,12 (k offset)

    const float* Ap = A + (size_t)(bm + lrow) * K + lk;
    const float* Wp = W + (size_t)(bn + lrow) * K + lk;

    double dacc[4][4];
#pragma unroll
    for (int i = 0; i < 4; i++)
#pragma unroll
        for (int j = 0; j < 4; j++) dacc[i][j] = 0.0;

    const int nch = K / BK;

    // prologue: stage chunk 0
    float4 aq = *(const float4*)(Ap);
    float4 bq = *(const float4*)(Wp);
    As[0][lk + 0][lrow] = aq.x; As[0][lk + 1][lrow] = aq.y;
    As[0][lk + 2][lrow] = aq.z; As[0][lk + 3][lrow] = aq.w;
    Bs[0][lk + 0][lrow] = bq.x; Bs[0][lk + 1][lrow] = bq.y;
    Bs[0][lk + 2][lrow] = bq.z; Bs[0][lk + 3][lrow] = bq.w;
    __syncthreads();

    for (int c = 0; c < nch; c++) {
        const int buf = c & 1;
        const bool more = (c + 1 < nch);
        if (more) {
            const int k0 = (c + 1) * BK;
            aq = *(const float4*)(Ap + k0);
            bq = *(const float4*)(Wp + k0);
        }

        float facc[4][4];
#pragma unroll
        for (int i = 0; i < 4; i++)
#pragma unroll
            for (int j = 0; j < 4; j++) facc[i][j] = 0.f;

#pragma unroll
        for (int k = 0; k < BK; k++) {
            float a[4], b[4];
            *(float4*)(a) = *(const float4*)(&As[buf][k][tr]);
            *(float4*)(b) = *(const float4*)(&Bs[buf][k][tc]);
#pragma unroll
            for (int i = 0; i < 4; i++)
#pragma unroll
                for (int j = 0; j < 4; j++)
                    facc[i][j] = fmaf(a[i], b[j], facc[i][j]);
        }
#pragma unroll
        for (int i = 0; i < 4; i++)
#pragma unroll
            for (int j = 0; j < 4; j++) dacc[i][j] += (double)facc[i][j];

        if (more) {
            __syncthreads();
            const int nb = buf ^ 1;
            As[nb][lk + 0][lrow] = aq.x; As[nb][lk + 1][lrow] = aq.y;
            As[nb][lk + 2][lrow] = aq.z; As[nb][lk + 3][lrow] = aq.w;
            Bs[nb][lk + 0][lrow] = bq.x; Bs[nb][lk + 1][lrow] = bq.y;
            Bs[nb][lk + 2][lrow] = bq.z; Bs[nb][lk + 3][lrow] = bq.w;
            __syncthreads();
        }
    }

    float bj[4];
#pragma unroll
    for (int j = 0; j < 4; j++) bj[j] = bias[bn + tc + j];
#pragma unroll
    for (int i = 0; i < 4; i++) {
        float* Cp = C + (size_t)(bm + tr + i) * N + bn + tc;
        float4 v = make_float4(__fadd_rn((float)dacc[i][0], bj[0]),
                               __fadd_rn((float)dacc[i][1], bj[1]),
                               __fadd_rn((float)dacc[i][2], bj[2]),
                               __fadd_rn((float)dacc[i][3], bj[3]));
        *(float4*)Cp = v;
    }
}

// ---------------- LN of padded int input -> X0 (double-precise stats) -------
__global__ void ln_input_kernel(const int* __restrict__ ids,
                                const float* __restrict__ gam,
                                const float* __restrict__ bet,
                                float* __restrict__ out)
{
    __shared__ float s[Lsz];
    __shared__ double red[256];
    const int r = blockIdx.x, tid = threadIdx.x;
    for (int j = tid; j < Lsz; j += 256)
        s[j] = (j < Ssz) ? (float)ids[(size_t)r * Ssz + j] : 0.f;
    __syncthreads();
    double p = 0.0;
    for (int j = tid; j < Lsz; j += 256) p += (double)s[j];
    red[tid] = p; __syncthreads();
    for (int o = 128; o > 0; o >>= 1) { if (tid < o) red[tid] += red[tid + o]; __syncthreads(); }
    const double mean = red[0] / (double)Lsz;
    const float  mf   = (float)mean;
    __syncthreads();
    double v = 0.0;
    for (int j = tid; j < Lsz; j += 256) { double d = (double)s[j] - mean; v += d * d; }
    red[tid] = v; __syncthreads();
    for (int o = 128; o > 0; o >>= 1) { if (tid < o) red[tid] += red[tid + o]; __syncthreads(); }
    const float vf  = (float)(red[0] / (double)Lsz);
    const float arg = __fadd_rn(vf, 1e-5f);
    const float rs  = (float)(1.0 / sqrt((double)arg));
    for (int j = tid; j < Lsz; j += 256) {
        float t = __fmul_rn(__fmul_rn(__fsub_rn(s[j], mf), rs), gam[j]);
        out[(size_t)r * Lsz + j] = __fadd_rn(t, bet[j]);
    }
}

// ---------------- LN + exact GELU (+ optional residual), per row ------------
__global__ void ln_gelu_kernel(const float* __restrict__ in,
                               const float* __restrict__ gam,
                               const float* __restrict__ bet,
                               const float* __restrict__ res,
                               float* __restrict__ out, int n)
{
    __shared__ float s[Lsz];
    __shared__ double red[256];
    const int r = blockIdx.x, tid = threadIdx.x;
    for (int j = tid; j < n; j += 256) s[j] = in[(size_t)r * n + j];
    __syncthreads();
    double p = 0.0;
    for (int j = tid; j < n; j += 256) p += (double)s[j];
    red[tid] = p; __syncthreads();
    for (int o = 128; o > 0; o >>= 1) { if (tid < o) red[tid] += red[tid + o]; __syncthreads(); }
    const double mean = red[0] / (double)n;
    const float  mf   = (float)mean;
    __syncthreads();
    double v = 0.0;
    for (int j = tid; j < n; j += 256) { double d = (double)s[j] - mean; v += d * d; }
    red[tid] = v; __syncthreads();
    for (int o = 128; o > 0; o >>= 1) { if (tid < o) red[tid] += red[tid + o]; __syncthreads(); }
    const float vf  = (float)(red[0] / (double)n);
    const float arg = __fadd_rn(vf, 1e-5f);
    const float rs  = (float)(1.0 / sqrt((double)arg));
    for (int j = tid; j < n; j += 256) {
        float x = __fadd_rn(__fmul_rn(__fmul_rn(__fsub_rn(s[j], mf), rs), gam[j]), bet[j]);
        double u = (double)x * 0.7071067811865475244;
        float e = (float)erf(u);
        float ge = __fmul_rn(__fmul_rn(x, __fadd_rn(e, 1.f)), 0.5f);
        float o = res ? __fadd_rn(ge, res[(size_t)r * n + j]) : ge;
        out[(size_t)r * n + j] = o;
    }
}

// ---------------- mu -> z = sigmoid(clip(mu,-5,5)), exact -------------------
__global__ void sigmoid_kernel(const float* __restrict__ mu, float* __restrict__ z)
{
    size_t i = (size_t)blockIdx.x * 256 + threadIdx.x;
    if (i < (size_t)Bsz * Lsz) {
        float m = mu[i];
        m = fminf(5.f, fmaxf(-5.f, m));
        z[i] = (float)(1.0 / (1.0 + exp(-(double)m)));
    }
}

// ---------------- column stats ----------------------------------------------
__global__ void colstats_kernel(const float* __restrict__ Z)
{
    const int j  = blockIdx.x * 256 + threadIdx.x;
    const int ch = blockIdx.y;
    const int r0 = ch * (Bsz / CCH);
    const bool hasN = (j < Lsz - 1);
    double s1 = 0, s2 = 0, s3 = 0;
    for (int r = r0; r < r0 + (Bsz / CCH); ++r) {
        float z  = Z[(size_t)r * Lsz + j];
        float zn = hasN ? Z[(size_t)r * Lsz + j + 1] : 0.f;
        s1 += (double)z;
        s2 += (double)z * (double)z;
        s3 += (double)z * (double)zn;
    }
    g_p1[ch * Lsz + j] = s1;
    g_p2[ch * Lsz + j] = s2;
    g_p3[ch * Lsz + j] = s3;
}

__global__ void colcombine_kernel()
{
    const int j = blockIdx.x * 256 + threadIdx.x;
    double s1 = 0, s2 = 0, s3 = 0;
    for (int c = 0; c < CCH; c++) {
        s1 += g_p1[c * Lsz + j];
        s2 += g_p2[c * Lsz + j];
        s3 += g_p3[c * Lsz + j];
    }
    g_S1[j] = s1; g_S2[j] = s2; g_S3[j] = s3;
}

// ---------------- adj (corr>0.5) + consistency term -------------------------
__global__ void adjcons_kernel(const float* __restrict__ fe)
{
    __shared__ double red[256];
    const int tid = threadIdx.x;
    double cons = 0.0;
    for (int j = tid; j < Lsz; j += 256) {
        double m = g_S1[j] / (double)Bsz;
        cons += fabs(m - (double)fe[j]);
        if (j < Lsz - 1) {
            double cov = g_S3[j] - g_S1[j] * g_S1[j + 1] / (double)Bsz;
            double v1  = g_S2[j]     - g_S1[j]     * g_S1[j]     / (double)Bsz;
            double v2  = g_S2[j + 1] - g_S1[j + 1] * g_S1[j + 1] / (double)Bsz;
            double den = v1 * v2;
            float a = 0.f;
            if (den > 0.0 && cov / sqrt(den) > 0.5) a = 1.f;
            g_adj[j] = a;
        }
    }
    red[tid] = cons; __syncthreads();
    for (int o = 128; o > 0; o >>= 1) { if (tid < o) red[tid] += red[tid + o]; __syncthreads(); }
    if (tid == 0) g_cons[0] = red[0];
}

// ---------------- per-row mask / top-k / outputs -----------------------------
__global__ void __launch_bounds__(256)
rowmask_kernel(const float* __restrict__ Z, const int* __restrict__ ids,
               float* __restrict__ outG, float* __restrict__ outZ)
{
    __shared__ float zs[Lsz];
    __shared__ float redf[256];
    __shared__ int   redi[256];
    __shared__ unsigned int hist[256];
    __shared__ unsigned int sh_prefix;
    __shared__ int sh_k;
    __shared__ int wsum[8];

    const int r = blockIdx.x, tid = threadIdx.x;
    for (int j = tid; j < Lsz; j += 256) zs[j] = Z[(size_t)r * Lsz + j];
    __syncthreads();

    float ent = 0.f, dif = 0.f;
    int cnt = 0;
    for (int j = tid; j < Lsz; j += 256) {
        float p = zs[j];
        ent += -(p * logf(__fadd_rn(p, 1e-7f)) +
                 (1.f - p) * logf(__fadd_rn(__fsub_rn(1.f, p), 1e-7f)));
        if (j < Lsz - 1) dif += fabsf(__fsub_rn(zs[j + 1], zs[j])) * g_adj[j];
        if (j < Ssz) {
            int tok = ids[(size_t)r * Ssz + j];
            if (p < 0.5f && tok != 0) cnt++;
        }
    }
    redf[tid] = ent; __syncthreads();
    for (int o = 128; o > 0; o >>= 1) { if (tid < o) redf[tid] += redf[tid + o]; __syncthreads(); }
    if (tid == 0) g_rowEnt[r] = redf[0];
    __syncthreads();
    redf[tid] = dif; __syncthreads();
    for (int o = 128; o > 0; o >>= 1) { if (tid < o) redf[tid] += redf[tid + o]; __syncthreads(); }
    if (tid == 0) g_rowDiff[r] = redf[0];
    __syncthreads();
    redi[tid] = cnt; __syncthreads();
    for (int o = 128; o > 0; o >>= 1) { if (tid < o) redi[tid] += redi[tid + o]; __syncthreads(); }
    const int total = redi[0];
    __syncthreads();
    const bool needfix = total > NEEDFIX_THRESH;

    unsigned int tsel = 0;
    int nEqKeep = 0;
    if (needfix) {
        unsigned int prefix = 0, highmask = 0;
        int k = MINTOK;
        for (int pass = 0; pass < 4; pass++) {
            const int shift = 24 - 8 * pass;
            hist[tid] = 0;
            __syncthreads();
            for (int j = tid; j < Ssz; j += 256) {
                unsigned int key = __float_as_uint(zs[j]);
                if ((key & highmask) == prefix)
                    atomicAdd(&hist[(key >> shift) & 0xFFu], 1u);
            }
            __syncthreads();
            if (tid == 0) {
                int cum = 0, b = 255;
                for (; b >= 0; --b) { cum += (int)hist[b]; if (cum >= k) break; }
                sh_k = k - (cum - (int)hist[b]);
                sh_prefix = prefix | ((unsigned int)b << shift);
            }
            __syncthreads();
            prefix = sh_prefix;
            k = sh_k;
            highmask |= 0xFFu << shift;
            __syncthreads();
        }
        tsel = prefix;
        int cg = 0;
        for (int j = tid; j < Ssz; j += 256)
            if (__float_as_uint(zs[j]) > tsel) cg++;
        redi[tid] = cg; __syncthreads();
        for (int o = 128; o > 0; o >>= 1) { if (tid < o) redi[tid] += redi[tid + o]; __syncthreads(); }
        nEqKeep = MINTOK - redi[0];
        __syncthreads();
    }

    int runEq = 0;
    for (int base = 0; base < Ssz; base += 256) {
        const int j = base + tid;
        const float zv = zs[j];
        const int tok = ids[(size_t)r * Ssz + j];
        bool m = (zv < 0.5f) && (tok != 0);
        if (needfix) {
            const unsigned int key = __float_as_uint(zv);
            const int eq = (key == tsel) ? 1 : 0;
            const unsigned int bal = __ballot_sync(0xffffffffu, eq);
            const int lane = tid & 31, w = tid >> 5;
            const int wexcl = __popc(bal & ((1u << lane) - 1u));
            if (lane == 31) wsum[w] = __popc(bal);
            __syncthreads();
            int woff = 0;
            for (int i = 0; i < w; i++) woff += wsum[i];
            const int excl = woff + wexcl;
            const bool keep = (key > tsel) || (eq && (runEq + excl) < nEqKeep);
            if (keep) m = false;
            __syncthreads();
            if (tid == 0) { int t = 0; for (int i = 0; i < 8; i++) t += wsum[i]; redi[0] = t; }
            __syncthreads();
            runEq += redi[0];
        }
        if (j == 0) m = false;
        outG[(size_t)r * Ssz + j] = m ? 0.f : (float)tok;
        outZ[(size_t)r * Ssz + j] = zv;
    }
}

// ---------------- final loss scalar -----------------------------------------
__global__ void finalize_kernel(float* __restrict__ out)
{
    __shared__ double red[256];
    const int tid = threadIdx.x;
    double e = 0, d = 0;
    for (int r = tid; r < Bsz; r += 256) {
        e += (double)g_rowEnt[r];
        d += (double)g_rowDiff[r];
    }
    red[tid] = e; __syncthreads();
    for (int o = 128; o > 0; o >>= 1) { if (tid < o) red[tid] += red[tid + o]; __syncthreads(); }
    const double entSum = red[0];
    __syncthreads();
    red[tid] = d; __syncthreads();
    for (int o = 128; o > 0; o >>= 1) { if (tid < o) red[tid] += red[tid + o]; __syncthreads(); }
    const double difSum = red[0];
    if (tid == 0) {
        double R1 = -0.001 * entSum / ((double)Bsz * (double)Lsz);
        double R2 =  0.001 * difSum / ((double)Bsz * (double)(Lsz - 1));
        double cons = 0.001 * g_cons[0] / (double)Lsz;
        out[(size_t)Bsz * Ssz] = (float)(R1 + R2 + cons);
    }
}

// ---------------- launch ------------------------------------------------------
extern "C" void kernel_launch(void* const* d_in, const int* in_sizes, int n_in,
                              void* d_out, int out_size)
{
    const float* in_g  = (const float*)d_in[0];
    const float* in_b  = (const float*)d_in[1];
    const float* wv    = (const float*)d_in[2];
    const float* bv    = (const float*)d_in[3];
    const float* wo    = (const float*)d_in[4];
    const float* bo    = (const float*)d_in[5];
    const float* w2    = (const float*)d_in[6];
    const float* b2    = (const float*)d_in[7];
    const float* g1    = (const float*)d_in[8];
    const float* be1   = (const float*)d_in[9];
    const float* w4    = (const float*)d_in[10];
    const float* b4    = (const float*)d_in[11];
    const float* g3    = (const float*)d_in[12];
    const float* be3   = (const float*)d_in[13];
    const float* w5    = (const float*)d_in[14];
    const float* b5    = (const float*)d_in[15];
    const float* g4    = (const float*)d_in[16];
    const float* be4   = (const float*)d_in[17];
    const float* w6    = (const float*)d_in[18];
    const float* b6    = (const float*)d_in[19];
    const float* g5    = (const float*)d_in[20];
    const float* be5   = (const float*)d_in[21];
    const float* w7    = (const float*)d_in[22];
    const float* b7    = (const float*)d_in[23];
    const float* g6    = (const float*)d_in[24];
    const float* be6   = (const float*)d_in[25];
    const float* wout  = (const float*)d_in[26];
    const float* bout  = (const float*)d_in[27];
    const float* fe    = (const float*)d_in[28];
    const int*   ids   = (const int*)d_in[29];
    float* out = (float*)d_out;

    float *pA, *pBf, *pC1, *pC2, *pC3, *pD1, *pD2;
    cudaGetSymbolAddress((void**)&pA,  g_A);
    cudaGetSymbolAddress((void**)&pBf, g_Bf);
    cudaGetSymbolAddress((void**)&pC1, g_C1);
    cudaGetSymbolAddress((void**)&pC2, g_C2);
    cudaGetSymbolAddress((void**)&pC3, g_C3);
    cudaGetSymbolAddress((void**)&pD1, g_D1);
    cudaGetSymbolAddress((void**)&pD2, g_D2);

    ln_input_kernel<<<Bsz, 256>>>(ids, in_g, in_b, pA);

    sgemm_nt<<<dim3(Lsz/64, Bsz/64), 256>>>(pA,  wv, bv, pBf, Bsz, Lsz, Lsz);
    sgemm_nt<<<dim3(Lsz/64, Bsz/64), 256>>>(pBf, wo, bo, pA,  Bsz, Lsz, Lsz);

    sgemm_nt<<<dim3(Hsz/64, Bsz/64), 256>>>(pA, w2, b2, pC1, Bsz, Hsz, Lsz);
    ln_gelu_kernel<<<Bsz, 256>>>(pC1, g1, be1, pC1, pC2, Hsz);

    sgemm_nt<<<dim3(Hsz/64, Bsz/64), 256>>>(pC2, w4, b4, pC3, Bsz, Hsz, Hsz);
    ln_gelu_kernel<<<Bsz, 256>>>(pC3, g3, be3, nullptr, pC3, Hsz);

    sgemm_nt<<<dim3(Hsz/64, Bsz/64), 256>>>(pC3, w5, b5, pC1, Bsz, Hsz, Hsz);
    ln_gelu_kernel<<<Bsz, 256>>>(pC1, g4, be4, pC2, pC1, Hsz);

    sgemm_nt<<<dim3((Hsz/2)/64, Bsz/64), 256>>>(pC1, w6, b6, pD1, Bsz, Hsz/2, Hsz);
    ln_gelu_kernel<<<Bsz, 256>>>(pD1, g5, be5, nullptr, pD1, Hsz/2);

    sgemm_nt<<<dim3((Hsz/4)/64, Bsz/64), 256>>>(pD1, w7, b7, pD2, Bsz, Hsz/4, Hsz/2);
    ln_gelu_kernel<<<Bsz, 256>>>(pD2, g6, be6, nullptr, pD2, Hsz/4);

    sgemm_nt<<<dim3(Lsz/64, Bsz/64), 256>>>(pD2, wout, bout, pBf, Bsz, Lsz, Hsz/4);
    sigmoid_kernel<<<(Bsz*Lsz)/256, 256>>>(pBf, pA);

    colstats_kernel<<<dim3(Lsz/256, CCH), 256>>>(pA);
    colcombine_kernel<<<Lsz/256, 256>>>();
    adjcons_kernel<<<1, 256>>>(fe);

    rowmask_kernel<<<Bsz, 256>>>(pA, ids, out, out + (size_t)Bsz * Ssz + 1);

    finalize_kernel<<<1, 256>>>(out);
}

// round 6
// speedup vs baseline: 4.0695x; 2.3889x over previous
#include <cuda_runtime.h>
#include <cuda_bf16.h>
#include <math.h>

// Problem constants
#define Bsz 4096
#define Ssz 1536
#define Lsz 2048
#define Hsz 1024
#define MINTOK 460                     // int(0.3*1536)
#define NEEDFIX_THRESH (Ssz - MINTOK)  // 1076

// ---------------- scratch (device globals; no allocations allowed) ----------
__device__ float g_A [(size_t)Bsz * Lsz];
__device__ float g_Bf[(size_t)Bsz * Lsz];
__device__ float g_C1[(size_t)Bsz * Hsz];
__device__ float g_C2[(size_t)Bsz * Hsz];
__device__ float g_C3[(size_t)Bsz * Hsz];
__device__ float g_D1[(size_t)Bsz * (Hsz/2)];
__device__ float g_D2[(size_t)Bsz * (Hsz/4)];

#define CCH 16
__device__ double g_p1[CCH * Lsz];
__device__ double g_p2[CCH * Lsz];
__device__ double g_p3[CCH * Lsz];
__device__ double g_S1[Lsz], g_S2[Lsz], g_S3[Lsz];
__device__ float  g_adj[Lsz];
__device__ float  g_rowEnt[Bsz], g_rowDiff[Bsz];
__device__ double g_cons[1];

// ---------------- GEMM: C[M,N] = A[M,K] @ W[N,K]^T + bias[N] ----------------
// Numerics: per output, fp32 FFMA over each ascending 64-k chunk; chunks folded
// (ascending) into a Kahan-compensated fp32 pair. No fp64 in the hot loop.
// Error ~1e-7 relative, far below the reference's own fp32 error.
// Perf: 64x64 tile, 4x4/thread, 256 threads, 2 CTAs/SM, double-buffered smem
// (BK=16 stages) + register prefetch.
__global__ void __launch_bounds__(256, 2)
sgemm_nt(const float* __restrict__ A, const float* __restrict__ W,
         const float* __restrict__ bias, float* __restrict__ C,
         int M, int N, int K)
{
    constexpr int BK = 16;
    __shared__ float As[2][BK][64 + 4];
    __shared__ float Bs[2][BK][64 + 4];
    const int tid = threadIdx.x;
    const int bm = blockIdx.y * 64;
    const int bn = blockIdx.x * 64;
    const int tr = (tid >> 4) << 2;     // 0..60 step 4 (C row offset)
    const int tc = (tid & 15) << 2;     // 0..60 step 4 (C col offset)

    const int lrow = tid & 63;          // tile row for loads
    const int lk   = (tid >> 6) << 2;   // 0,4,8,12 (k offset)

    const float* Ap = A + (size_t)(bm + lrow) * K + lk;
    const float* Wp = W + (size_t)(bn + lrow) * K + lk;

    float ksum[4][4], kcmp[4][4], facc[4][4];
#pragma unroll
    for (int i = 0; i < 4; i++)
#pragma unroll
        for (int j = 0; j < 4; j++) {
            ksum[i][j] = 0.f; kcmp[i][j] = 0.f; facc[i][j] = 0.f;
        }

    const int nch = K / BK;   // number of 16-k stages; fold every 4 stages

    // prologue: stage chunk 0
    float4 aq = *(const float4*)(Ap);
    float4 bq = *(const float4*)(Wp);
    As[0][lk + 0][lrow] = aq.x; As[0][lk + 1][lrow] = aq.y;
    As[0][lk + 2][lrow] = aq.z; As[0][lk + 3][lrow] = aq.w;
    Bs[0][lk + 0][lrow] = bq.x; Bs[0][lk + 1][lrow] = bq.y;
    Bs[0][lk + 2][lrow] = bq.z; Bs[0][lk + 3][lrow] = bq.w;
    __syncthreads();

    for (int c = 0; c < nch; c++) {
        const int buf = c & 1;
        const bool more = (c + 1 < nch);
        if (more) {
            const int k0 = (c + 1) * BK;
            aq = *(const float4*)(Ap + k0);
            bq = *(const float4*)(Wp + k0);
        }

#pragma unroll
        for (int k = 0; k < BK; k++) {
            float a[4], b[4];
            *(float4*)(a) = *(const float4*)(&As[buf][k][tr]);
            *(float4*)(b) = *(const float4*)(&Bs[buf][k][tc]);
#pragma unroll
            for (int i = 0; i < 4; i++)
#pragma unroll
                for (int j = 0; j < 4; j++)
                    facc[i][j] = fmaf(a[i], b[j], facc[i][j]);
        }

        if ((c & 3) == 3) {
            // Kahan fold of the 64-k chunk into (ksum, kcmp)
#pragma unroll
            for (int i = 0; i < 4; i++)
#pragma unroll
                for (int j = 0; j < 4; j++) {
                    const float y = facc[i][j];
                    const float t = __fadd_rn(ksum[i][j], y);
                    const float e = __fadd_rn(__fsub_rn(ksum[i][j], t), y);
                    kcmp[i][j] = __fadd_rn(kcmp[i][j], e);
                    ksum[i][j] = t;
                    facc[i][j] = 0.f;
                }
        }

        if (more) {
            __syncthreads();
            const int nb = buf ^ 1;
            As[nb][lk + 0][lrow] = aq.x; As[nb][lk + 1][lrow] = aq.y;
            As[nb][lk + 2][lrow] = aq.z; As[nb][lk + 3][lrow] = aq.w;
            Bs[nb][lk + 0][lrow] = bq.x; Bs[nb][lk + 1][lrow] = bq.y;
            Bs[nb][lk + 2][lrow] = bq.z; Bs[nb][lk + 3][lrow] = bq.w;
            __syncthreads();
        }
    }

    float bj[4];
#pragma unroll
    for (int j = 0; j < 4; j++) bj[j] = bias[bn + tc + j];
#pragma unroll
    for (int i = 0; i < 4; i++) {
        float* Cp = C + (size_t)(bm + tr + i) * N + bn + tc;
        float4 v;
        v.x = __fadd_rn(__fadd_rn(ksum[i][0], kcmp[i][0]), bj[0]);
        v.y = __fadd_rn(__fadd_rn(ksum[i][1], kcmp[i][1]), bj[1]);
        v.z = __fadd_rn(__fadd_rn(ksum[i][2], kcmp[i][2]), bj[2]);
        v.w = __fadd_rn(__fadd_rn(ksum[i][3], kcmp[i][3]), bj[3]);
        *(float4*)Cp = v;
    }
}

// ---------------- LN of padded int input -> X0 (double-precise stats) -------
__global__ void ln_input_kernel(const int* __restrict__ ids,
                                const float* __restrict__ gam,
                                const float* __restrict__ bet,
                                float* __restrict__ out)
{
    __shared__ float s[Lsz];
    __shared__ double red[256];
    const int r = blockIdx.x, tid = threadIdx.x;
    for (int j = tid; j < Lsz; j += 256)
        s[j] = (j < Ssz) ? (float)ids[(size_t)r * Ssz + j] : 0.f;
    __syncthreads();
    double p = 0.0;
    for (int j = tid; j < Lsz; j += 256) p += (double)s[j];
    red[tid] = p; __syncthreads();
    for (int o = 128; o > 0; o >>= 1) { if (tid < o) red[tid] += red[tid + o]; __syncthreads(); }
    const double mean = red[0] / (double)Lsz;
    const float  mf   = (float)mean;
    __syncthreads();
    double v = 0.0;
    for (int j = tid; j < Lsz; j += 256) { double d = (double)s[j] - mean; v += d * d; }
    red[tid] = v; __syncthreads();
    for (int o = 128; o > 0; o >>= 1) { if (tid < o) red[tid] += red[tid + o]; __syncthreads(); }
    const float vf  = (float)(red[0] / (double)Lsz);
    const float arg = __fadd_rn(vf, 1e-5f);
    const float rs  = (float)(1.0 / sqrt((double)arg));
    for (int j = tid; j < Lsz; j += 256) {
        float t = __fmul_rn(__fmul_rn(__fsub_rn(s[j], mf), rs), gam[j]);
        out[(size_t)r * Lsz + j] = __fadd_rn(t, bet[j]);
    }
}

// ---------------- LN + exact GELU (+ optional residual), per row ------------
__global__ void ln_gelu_kernel(const float* __restrict__ in,
                               const float* __restrict__ gam,
                               const float* __restrict__ bet,
                               const float* __restrict__ res,
                               float* __restrict__ out, int n)
{
    __shared__ float s[Lsz];
    __shared__ double red[256];
    const int r = blockIdx.x, tid = threadIdx.x;
    for (int j = tid; j < n; j += 256) s[j] = in[(size_t)r * n + j];
    __syncthreads();
    double p = 0.0;
    for (int j = tid; j < n; j += 256) p += (double)s[j];
    red[tid] = p; __syncthreads();
    for (int o = 128; o > 0; o >>= 1) { if (tid < o) red[tid] += red[tid + o]; __syncthreads(); }
    const double mean = red[0] / (double)n;
    const float  mf   = (float)mean;
    __syncthreads();
    double v = 0.0;
    for (int j = tid; j < n; j += 256) { double d = (double)s[j] - mean; v += d * d; }
    red[tid] = v; __syncthreads();
    for (int o = 128; o > 0; o >>= 1) { if (tid < o) red[tid] += red[tid + o]; __syncthreads(); }
    const float vf  = (float)(red[0] / (double)n);
    const float arg = __fadd_rn(vf, 1e-5f);
    const float rs  = (float)(1.0 / sqrt((double)arg));
    for (int j = tid; j < n; j += 256) {
        float x = __fadd_rn(__fmul_rn(__fmul_rn(__fsub_rn(s[j], mf), rs), gam[j]), bet[j]);
        double u = (double)x * 0.7071067811865475244;
        float e = (float)erf(u);
        float ge = __fmul_rn(__fmul_rn(x, __fadd_rn(e, 1.f)), 0.5f);
        float o = res ? __fadd_rn(ge, res[(size_t)r * n + j]) : ge;
        out[(size_t)r * n + j] = o;
    }
}

// ---------------- mu -> z = sigmoid(clip(mu,-5,5)), exact -------------------
__global__ void sigmoid_kernel(const float* __restrict__ mu, float* __restrict__ z)
{
    size_t i = (size_t)blockIdx.x * 256 + threadIdx.x;
    if (i < (size_t)Bsz * Lsz) {
        float m = mu[i];
        m = fminf(5.f, fmaxf(-5.f, m));
        z[i] = (float)(1.0 / (1.0 + exp(-(double)m)));
    }
}

// ---------------- column stats ----------------------------------------------
__global__ void colstats_kernel(const float* __restrict__ Z)
{
    const int j  = blockIdx.x * 256 + threadIdx.x;
    const int ch = blockIdx.y;
    const int r0 = ch * (Bsz / CCH);
    const bool hasN = (j < Lsz - 1);
    double s1 = 0, s2 = 0, s3 = 0;
    for (int r = r0; r < r0 + (Bsz / CCH); ++r) {
        float z  = Z[(size_t)r * Lsz + j];
        float zn = hasN ? Z[(size_t)r * Lsz + j + 1] : 0.f;
        s1 += (double)z;
        s2 += (double)z * (double)z;
        s3 += (double)z * (double)zn;
    }
    g_p1[ch * Lsz + j] = s1;
    g_p2[ch * Lsz + j] = s2;
    g_p3[ch * Lsz + j] = s3;
}

__global__ void colcombine_kernel()
{
    const int j = blockIdx.x * 256 + threadIdx.x;
    double s1 = 0, s2 = 0, s3 = 0;
    for (int c = 0; c < CCH; c++) {
        s1 += g_p1[c * Lsz + j];
        s2 += g_p2[c * Lsz + j];
        s3 += g_p3[c * Lsz + j];
    }
    g_S1[j] = s1; g_S2[j] = s2; g_S3[j] = s3;
}

// ---------------- adj (corr>0.5) + consistency term -------------------------
__global__ void adjcons_kernel(const float* __restrict__ fe)
{
    __shared__ double red[256];
    const int tid = threadIdx.x;
    double cons = 0.0;
    for (int j = tid; j < Lsz; j += 256) {
        double m = g_S1[j] / (double)Bsz;
        cons += fabs(m - (double)fe[j]);
        if (j < Lsz - 1) {
            double cov = g_S3[j] - g_S1[j] * g_S1[j + 1] / (double)Bsz;
            double v1  = g_S2[j]     - g_S1[j]     * g_S1[j]     / (double)Bsz;
            double v2  = g_S2[j + 1] - g_S1[j + 1] * g_S1[j + 1] / (double)Bsz;
            double den = v1 * v2;
            float a = 0.f;
            if (den > 0.0 && cov / sqrt(den) > 0.5) a = 1.f;
            g_adj[j] = a;
        }
    }
    red[tid] = cons; __syncthreads();
    for (int o = 128; o > 0; o >>= 1) { if (tid < o) red[tid] += red[tid + o]; __syncthreads(); }
    if (tid == 0) g_cons[0] = red[0];
}

// ---------------- per-row mask / top-k / outputs -----------------------------
__global__ void __launch_bounds__(256)
rowmask_kernel(const float* __restrict__ Z, const int* __restrict__ ids,
               float* __restrict__ outG, float* __restrict__ outZ)
{
    __shared__ float zs[Lsz];
    __shared__ float redf[256];
    __shared__ int   redi[256];
    __shared__ unsigned int hist[256];
    __shared__ unsigned int sh_prefix;
    __shared__ int sh_k;
    __shared__ int wsum[8];

    const int r = blockIdx.x, tid = threadIdx.x;
    for (int j = tid; j < Lsz; j += 256) zs[j] = Z[(size_t)r * Lsz + j];
    __syncthreads();

    float ent = 0.f, dif = 0.f;
    int cnt = 0;
    for (int j = tid; j < Lsz; j += 256) {
        float p = zs[j];
        ent += -(p * logf(__fadd_rn(p, 1e-7f)) +
                 (1.f - p) * logf(__fadd_rn(__fsub_rn(1.f, p), 1e-7f)));
        if (j < Lsz - 1) dif += fabsf(__fsub_rn(zs[j + 1], zs[j])) * g_adj[j];
        if (j < Ssz) {
            int tok = ids[(size_t)r * Ssz + j];
            if (p < 0.5f && tok != 0) cnt++;
        }
    }
    redf[tid] = ent; __syncthreads();
    for (int o = 128; o > 0; o >>= 1) { if (tid < o) redf[tid] += redf[tid + o]; __syncthreads(); }
    if (tid == 0) g_rowEnt[r] = redf[0];
    __syncthreads();
    redf[tid] = dif; __syncthreads();
    for (int o = 128; o > 0; o >>= 1) { if (tid < o) redf[tid] += redf[tid + o]; __syncthreads(); }
    if (tid == 0) g_rowDiff[r] = redf[0];
    __syncthreads();
    redi[tid] = cnt; __syncthreads();
    for (int o = 128; o > 0; o >>= 1) { if (tid < o) redi[tid] += redi[tid + o]; __syncthreads(); }
    const int total = redi[0];
    __syncthreads();
    const bool needfix = total > NEEDFIX_THRESH;

    unsigned int tsel = 0;
    int nEqKeep = 0;
    if (needfix) {
        unsigned int prefix = 0, highmask = 0;
        int k = MINTOK;
        for (int pass = 0; pass < 4; pass++) {
            const int shift = 24 - 8 * pass;
            hist[tid] = 0;
            __syncthreads();
            for (int j = tid; j < Ssz; j += 256) {
                unsigned int key = __float_as_uint(zs[j]);
                if ((key & highmask) == prefix)
                    atomicAdd(&hist[(key >> shift) & 0xFFu], 1u);
            }
            __syncthreads();
            if (tid == 0) {
                int cum = 0, b = 255;
                for (; b >= 0; --b) { cum += (int)hist[b]; if (cum >= k) break; }
                sh_k = k - (cum - (int)hist[b]);
                sh_prefix = prefix | ((unsigned int)b << shift);
            }
            __syncthreads();
            prefix = sh_prefix;
            k = sh_k;
            highmask |= 0xFFu << shift;
            __syncthreads();
        }
        tsel = prefix;
        int cg = 0;
        for (int j = tid; j < Ssz; j += 256)
            if (__float_as_uint(zs[j]) > tsel) cg++;
        redi[tid] = cg; __syncthreads();
        for (int o = 128; o > 0; o >>= 1) { if (tid < o) redi[tid] += redi[tid + o]; __syncthreads(); }
        nEqKeep = MINTOK - redi[0];
        __syncthreads();
    }

    int runEq = 0;
    for (int base = 0; base < Ssz; base += 256) {
        const int j = base + tid;
        const float zv = zs[j];
        const int tok = ids[(size_t)r * Ssz + j];
        bool m = (zv < 0.5f) && (tok != 0);
        if (needfix) {
            const unsigned int key = __float_as_uint(zv);
            const int eq = (key == tsel) ? 1 : 0;
            const unsigned int bal = __ballot_sync(0xffffffffu, eq);
            const int lane = tid & 31, w = tid >> 5;
            const int wexcl = __popc(bal & ((1u << lane) - 1u));
            if (lane == 31) wsum[w] = __popc(bal);
            __syncthreads();
            int woff = 0;
            for (int i = 0; i < w; i++) woff += wsum[i];
            const int excl = woff + wexcl;
            const bool keep = (key > tsel) || (eq && (runEq + excl) < nEqKeep);
            if (keep) m = false;
            __syncthreads();
            if (tid == 0) { int t = 0; for (int i = 0; i < 8; i++) t += wsum[i]; redi[0] = t; }
            __syncthreads();
            runEq += redi[0];
        }
        if (j == 0) m = false;
        outG[(size_t)r * Ssz + j] = m ? 0.f : (float)tok;
        outZ[(size_t)r * Ssz + j] = zv;
    }
}

// ---------------- final loss scalar -----------------------------------------
__global__ void finalize_kernel(float* __restrict__ out)
{
    __shared__ double red[256];
    const int tid = threadIdx.x;
    double e = 0, d = 0;
    for (int r = tid; r < Bsz; r += 256) {
        e += (double)g_rowEnt[r];
        d += (double)g_rowDiff[r];
    }
    red[tid] = e; __syncthreads();
    for (int o = 128; o > 0; o >>= 1) { if (tid < o) red[tid] += red[tid + o]; __syncthreads(); }
    const double entSum = red[0];
    __syncthreads();
    red[tid] = d; __syncthreads();
    for (int o = 128; o > 0; o >>= 1) { if (tid < o) red[tid] += red[tid + o]; __syncthreads(); }
    const double difSum = red[0];
    if (tid == 0) {
        double R1 = -0.001 * entSum / ((double)Bsz * (double)Lsz);
        double R2 =  0.001 * difSum / ((double)Bsz * (double)(Lsz - 1));
        double cons = 0.001 * g_cons[0] / (double)Lsz;
        out[(size_t)Bsz * Ssz] = (float)(R1 + R2 + cons);
    }
}

// ---------------- launch ------------------------------------------------------
extern "C" void kernel_launch(void* const* d_in, const int* in_sizes, int n_in,
                              void* d_out, int out_size)
{
    const float* in_g  = (const float*)d_in[0];
    const float* in_b  = (const float*)d_in[1];
    const float* wv    = (const float*)d_in[2];
    const float* bv    = (const float*)d_in[3];
    const float* wo    = (const float*)d_in[4];
    const float* bo    = (const float*)d_in[5];
    const float* w2    = (const float*)d_in[6];
    const float* b2    = (const float*)d_in[7];
    const float* g1    = (const float*)d_in[8];
    const float* be1   = (const float*)d_in[9];
    const float* w4    = (const float*)d_in[10];
    const float* b4    = (const float*)d_in[11];
    const float* g3    = (const float*)d_in[12];
    const float* be3   = (const float*)d_in[13];
    const float* w5    = (const float*)d_in[14];
    const float* b5    = (const float*)d_in[15];
    const float* g4    = (const float*)d_in[16];
    const float* be4   = (const float*)d_in[17];
    const float* w6    = (const float*)d_in[18];
    const float* b6    = (const float*)d_in[19];
    const float* g5    = (const float*)d_in[20];
    const float* be5   = (const float*)d_in[21];
    const float* w7    = (const float*)d_in[22];
    const float* b7    = (const float*)d_in[23];
    const float* g6    = (const float*)d_in[24];
    const float* be6   = (const float*)d_in[25];
    const float* wout  = (const float*)d_in[26];
    const float* bout  = (const float*)d_in[27];
    const float* fe    = (const float*)d_in[28];
    const int*   ids   = (const int*)d_in[29];
    float* out = (float*)d_out;

    float *pA, *pBf, *pC1, *pC2, *pC3, *pD1, *pD2;
    cudaGetSymbolAddress((void**)&pA,  g_A);
    cudaGetSymbolAddress((void**)&pBf, g_Bf);
    cudaGetSymbolAddress((void**)&pC1, g_C1);
    cudaGetSymbolAddress((void**)&pC2, g_C2);
    cudaGetSymbolAddress((void**)&pC3, g_C3);
    cudaGetSymbolAddress((void**)&pD1, g_D1);
    cudaGetSymbolAddress((void**)&pD2, g_D2);

    ln_input_kernel<<<Bsz, 256>>>(ids, in_g, in_b, pA);

    sgemm_nt<<<dim3(Lsz/64, Bsz/64), 256>>>(pA,  wv, bv, pBf, Bsz, Lsz, Lsz);
    sgemm_nt<<<dim3(Lsz/64, Bsz/64), 256>>>(pBf, wo, bo, pA,  Bsz, Lsz, Lsz);

    sgemm_nt<<<dim3(Hsz/64, Bsz/64), 256>>>(pA, w2, b2, pC1, Bsz, Hsz, Lsz);
    ln_gelu_kernel<<<Bsz, 256>>>(pC1, g1, be1, pC1, pC2, Hsz);

    sgemm_nt<<<dim3(Hsz/64, Bsz/64), 256>>>(pC2, w4, b4, pC3, Bsz, Hsz, Hsz);
    ln_gelu_kernel<<<Bsz, 256>>>(pC3, g3, be3, nullptr, pC3, Hsz);

    sgemm_nt<<<dim3(Hsz/64, Bsz/64), 256>>>(pC3, w5, b5, pC1, Bsz, Hsz, Hsz);
    ln_gelu_kernel<<<Bsz, 256>>>(pC1, g4, be4, pC2, pC1, Hsz);

    sgemm_nt<<<dim3((Hsz/2)/64, Bsz/64), 256>>>(pC1, w6, b6, pD1, Bsz, Hsz/2, Hsz);
    ln_gelu_kernel<<<Bsz, 256>>>(pD1, g5, be5, nullptr, pD1, Hsz/2);

    sgemm_nt<<<dim3((Hsz/4)/64, Bsz/64), 256>>>(pD1, w7, b7, pD2, Bsz, Hsz/4, Hsz/2);
    ln_gelu_kernel<<<Bsz, 256>>>(pD2, g6, be6, nullptr, pD2, Hsz/4);

    sgemm_nt<<<dim3(Lsz/64, Bsz/64), 256>>>(pD2, wout, bout, pBf, Bsz, Lsz, Hsz/4);
    sigmoid_kernel<<<(Bsz*Lsz)/256, 256>>>(pBf, pA);

    colstats_kernel<<<dim3(Lsz/256, CCH), 256>>>(pA);
    colcombine_kernel<<<Lsz/256, 256>>>();
    adjcons_kernel<<<1, 256>>>(fe);

    rowmask_kernel<<<Bsz, 256>>>(pA, ids, out, out + (size_t)Bsz * Ssz + 1);

    finalize_kernel<<<1, 256>>>(out);
}

// round 7
// speedup vs baseline: 5.2916x; 1.3003x over previous
#include <cuda_runtime.h>
#include <cuda_bf16.h>
#include <math.h>

// Problem constants
#define Bsz 4096
#define Ssz 1536
#define Lsz 2048
#define Hsz 1024
#define MINTOK 460                     // int(0.3*1536)
#define NEEDFIX_THRESH (Ssz - MINTOK)  // 1076

// ---------------- scratch (device globals; no allocations allowed) ----------
__device__ float g_A [(size_t)Bsz * Lsz];
__device__ float g_Bf[(size_t)Bsz * Lsz];
__device__ float g_C1[(size_t)Bsz * Hsz];
__device__ float g_C2[(size_t)Bsz * Hsz];
__device__ float g_C3[(size_t)Bsz * Hsz];
__device__ float g_D1[(size_t)Bsz * (Hsz/2)];
__device__ float g_D2[(size_t)Bsz * (Hsz/4)];

#define CCH 16
__device__ double g_p1[CCH * Lsz];
__device__ double g_p2[CCH * Lsz];
__device__ double g_p3[CCH * Lsz];
__device__ double g_S1[Lsz], g_S2[Lsz], g_S3[Lsz];
__device__ float  g_adj[Lsz];
__device__ float  g_rowEnt[Bsz], g_rowDiff[Bsz];
__device__ double g_cons[1];

// ---------------- GEMM: C[M,N] = A[M,K] @ W[N,K]^T + bias[N] ----------------
// Numerics contract (frozen, bitwise-identical to round 6): per output, fp32
// FFMA over each ascending 64-k chunk; chunks folded ascending into a Kahan
// (ksum, kcmp) fp32 pair; (ksum+kcmp)+bias at the end.
// Perf: 64x64 tile, 4x4/thread, 256 threads, BK=32 stages (sync every 32 k,
// fold every 2 stages), double-buffered smem + register prefetch, 2 CTAs/SM.
__global__ void __launch_bounds__(256)
sgemm_nt(const float* __restrict__ A, const float* __restrict__ W,
         const float* __restrict__ bias, float* __restrict__ C,
         int M, int N, int K)
{
    constexpr int BK = 32;
    __shared__ float As[2][BK][64 + 4];
    __shared__ float Bs[2][BK][64 + 4];
    const int tid = threadIdx.x;
    const int bm = blockIdx.y * 64;
    const int bn = blockIdx.x * 64;
    const int tr = (tid >> 4) << 2;     // 0..60 step 4 (C row offset)
    const int tc = (tid & 15) << 2;     // 0..60 step 4 (C col offset)

    const int lrow = tid & 63;          // tile row for loads
    const int lk   = (tid >> 6) << 2;   // 0,4,8,12 (k offset; +16 for 2nd quad)

    const float* Ap = A + (size_t)(bm + lrow) * K + lk;
    const float* Wp = W + (size_t)(bn + lrow) * K + lk;

    float ksum[4][4], kcmp[4][4], facc[4][4];
#pragma unroll
    for (int i = 0; i < 4; i++)
#pragma unroll
        for (int j = 0; j < 4; j++) {
            ksum[i][j] = 0.f; kcmp[i][j] = 0.f; facc[i][j] = 0.f;
        }

    const int nch = K / BK;   // 32-k stages; Kahan fold every 2 stages (64 k)

    // prologue: stage chunk 0
    float4 aq0 = *(const float4*)(Ap);
    float4 aq1 = *(const float4*)(Ap + 16);
    float4 bq0 = *(const float4*)(Wp);
    float4 bq1 = *(const float4*)(Wp + 16);
    As[0][lk + 0][lrow] = aq0.x; As[0][lk + 1][lrow] = aq0.y;
    As[0][lk + 2][lrow] = aq0.z; As[0][lk + 3][lrow] = aq0.w;
    As[0][lk + 16][lrow] = aq1.x; As[0][lk + 17][lrow] = aq1.y;
    As[0][lk + 18][lrow] = aq1.z; As[0][lk + 19][lrow] = aq1.w;
    Bs[0][lk + 0][lrow] = bq0.x; Bs[0][lk + 1][lrow] = bq0.y;
    Bs[0][lk + 2][lrow] = bq0.z; Bs[0][lk + 3][lrow] = bq0.w;
    Bs[0][lk + 16][lrow] = bq1.x; Bs[0][lk + 17][lrow] = bq1.y;
    Bs[0][lk + 18][lrow] = bq1.z; Bs[0][lk + 19][lrow] = bq1.w;
    __syncthreads();

    for (int c = 0; c < nch; c++) {
        const int buf = c & 1;
        const bool more = (c + 1 < nch);
        if (more) {
            const int k0 = (c + 1) * BK;
            aq0 = *(const float4*)(Ap + k0);
            aq1 = *(const float4*)(Ap + k0 + 16);
            bq0 = *(const float4*)(Wp + k0);
            bq1 = *(const float4*)(Wp + k0 + 16);
        }

#pragma unroll
        for (int k = 0; k < BK; k++) {
            float a[4], b[4];
            *(float4*)(a) = *(const float4*)(&As[buf][k][tr]);
            *(float4*)(b) = *(const float4*)(&Bs[buf][k][tc]);
#pragma unroll
            for (int i = 0; i < 4; i++)
#pragma unroll
                for (int j = 0; j < 4; j++)
                    facc[i][j] = fmaf(a[i], b[j], facc[i][j]);
        }

        if ((c & 1) == 1) {
            // Kahan fold of the completed 64-k chunk into (ksum, kcmp)
#pragma unroll
            for (int i = 0; i < 4; i++)
#pragma unroll
                for (int j = 0; j < 4; j++) {
                    const float y = facc[i][j];
                    const float t = __fadd_rn(ksum[i][j], y);
                    const float e = __fadd_rn(__fsub_rn(ksum[i][j], t), y);
                    kcmp[i][j] = __fadd_rn(kcmp[i][j], e);
                    ksum[i][j] = t;
                    facc[i][j] = 0.f;
                }
        }

        if (more) {
            __syncthreads();
            const int nb = buf ^ 1;
            As[nb][lk + 0][lrow] = aq0.x; As[nb][lk + 1][lrow] = aq0.y;
            As[nb][lk + 2][lrow] = aq0.z; As[nb][lk + 3][lrow] = aq0.w;
            As[nb][lk + 16][lrow] = aq1.x; As[nb][lk + 17][lrow] = aq1.y;
            As[nb][lk + 18][lrow] = aq1.z; As[nb][lk + 19][lrow] = aq1.w;
            Bs[nb][lk + 0][lrow] = bq0.x; Bs[nb][lk + 1][lrow] = bq0.y;
            Bs[nb][lk + 2][lrow] = bq0.z; Bs[nb][lk + 3][lrow] = bq0.w;
            Bs[nb][lk + 16][lrow] = bq1.x; Bs[nb][lk + 17][lrow] = bq1.y;
            Bs[nb][lk + 18][lrow] = bq1.z; Bs[nb][lk + 19][lrow] = bq1.w;
            __syncthreads();
        }
    }

    float bj[4];
#pragma unroll
    for (int j = 0; j < 4; j++) bj[j] = bias[bn + tc + j];
#pragma unroll
    for (int i = 0; i < 4; i++) {
        float* Cp = C + (size_t)(bm + tr + i) * N + bn + tc;
        float4 v;
        v.x = __fadd_rn(__fadd_rn(ksum[i][0], kcmp[i][0]), bj[0]);
        v.y = __fadd_rn(__fadd_rn(ksum[i][1], kcmp[i][1]), bj[1]);
        v.z = __fadd_rn(__fadd_rn(ksum[i][2], kcmp[i][2]), bj[2]);
        v.w = __fadd_rn(__fadd_rn(ksum[i][3], kcmp[i][3]), bj[3]);
        *(float4*)Cp = v;
    }
}

// ---------------- LN of padded int input -> X0 (double-precise stats) -------
__global__ void ln_input_kernel(const int* __restrict__ ids,
                                const float* __restrict__ gam,
                                const float* __restrict__ bet,
                                float* __restrict__ out)
{
    __shared__ float s[Lsz];
    __shared__ double red[256];
    const int r = blockIdx.x, tid = threadIdx.x;
    for (int j = tid; j < Lsz; j += 256)
        s[j] = (j < Ssz) ? (float)ids[(size_t)r * Ssz + j] : 0.f;
    __syncthreads();
    double p = 0.0;
    for (int j = tid; j < Lsz; j += 256) p += (double)s[j];
    red[tid] = p; __syncthreads();
    for (int o = 128; o > 0; o >>= 1) { if (tid < o) red[tid] += red[tid + o]; __syncthreads(); }
    const double mean = red[0] / (double)Lsz;
    const float  mf   = (float)mean;
    __syncthreads();
    double v = 0.0;
    for (int j = tid; j < Lsz; j += 256) { double d = (double)s[j] - mean; v += d * d; }
    red[tid] = v; __syncthreads();
    for (int o = 128; o > 0; o >>= 1) { if (tid < o) red[tid] += red[tid + o]; __syncthreads(); }
    const float vf  = (float)(red[0] / (double)Lsz);
    const float arg = __fadd_rn(vf, 1e-5f);
    const float rs  = (float)(1.0 / sqrt((double)arg));
    for (int j = tid; j < Lsz; j += 256) {
        float t = __fmul_rn(__fmul_rn(__fsub_rn(s[j], mf), rs), gam[j]);
        out[(size_t)r * Lsz + j] = __fadd_rn(t, bet[j]);
    }
}

// ---------------- LN + exact GELU (+ optional residual), per row ------------
__global__ void ln_gelu_kernel(const float* __restrict__ in,
                               const float* __restrict__ gam,
                               const float* __restrict__ bet,
                               const float* __restrict__ res,
                               float* __restrict__ out, int n)
{
    __shared__ float s[Lsz];
    __shared__ double red[256];
    const int r = blockIdx.x, tid = threadIdx.x;
    for (int j = tid; j < n; j += 256) s[j] = in[(size_t)r * n + j];
    __syncthreads();
    double p = 0.0;
    for (int j = tid; j < n; j += 256) p += (double)s[j];
    red[tid] = p; __syncthreads();
    for (int o = 128; o > 0; o >>= 1) { if (tid < o) red[tid] += red[tid + o]; __syncthreads(); }
    const double mean = red[0] / (double)n;
    const float  mf   = (float)mean;
    __syncthreads();
    double v = 0.0;
    for (int j = tid; j < n; j += 256) { double d = (double)s[j] - mean; v += d * d; }
    red[tid] = v; __syncthreads();
    for (int o = 128; o > 0; o >>= 1) { if (tid < o) red[tid] += red[tid + o]; __syncthreads(); }
    const float vf  = (float)(red[0] / (double)n);
    const float arg = __fadd_rn(vf, 1e-5f);
    const float rs  = (float)(1.0 / sqrt((double)arg));
    for (int j = tid; j < n; j += 256) {
        float x = __fadd_rn(__fmul_rn(__fmul_rn(__fsub_rn(s[j], mf), rs), gam[j]), bet[j]);
        float u = __fmul_rn(x, 0.70710678118654752f);
        float e = erff(u);
        float ge = __fmul_rn(__fmul_rn(x, __fadd_rn(e, 1.f)), 0.5f);
        float o = res ? __fadd_rn(ge, res[(size_t)r * n + j]) : ge;
        out[(size_t)r * n + j] = o;
    }
}

// ---------------- mu -> z = sigmoid(clip(mu,-5,5)), exact -------------------
__global__ void sigmoid_kernel(const float* __restrict__ mu, float* __restrict__ z)
{
    size_t i = (size_t)blockIdx.x * 256 + threadIdx.x;
    if (i < (size_t)Bsz * Lsz) {
        float m = mu[i];
        m = fminf(5.f, fmaxf(-5.f, m));
        z[i] = (float)(1.0 / (1.0 + exp(-(double)m)));
    }
}

// ---------------- column stats ----------------------------------------------
__global__ void colstats_kernel(const float* __restrict__ Z)
{
    const int j  = blockIdx.x * 256 + threadIdx.x;
    const int ch = blockIdx.y;
    const int r0 = ch * (Bsz / CCH);
    const bool hasN = (j < Lsz - 1);
    double s1 = 0, s2 = 0, s3 = 0;
    for (int r = r0; r < r0 + (Bsz / CCH); ++r) {
        float z  = Z[(size_t)r * Lsz + j];
        float zn = hasN ? Z[(size_t)r * Lsz + j + 1] : 0.f;
        s1 += (double)z;
        s2 += (double)z * (double)z;
        s3 += (double)z * (double)zn;
    }
    g_p1[ch * Lsz + j] = s1;
    g_p2[ch * Lsz + j] = s2;
    g_p3[ch * Lsz + j] = s3;
}

__global__ void colcombine_kernel()
{
    const int j = blockIdx.x * 256 + threadIdx.x;
    double s1 = 0, s2 = 0, s3 = 0;
    for (int c = 0; c < CCH; c++) {
        s1 += g_p1[c * Lsz + j];
        s2 += g_p2[c * Lsz + j];
        s3 += g_p3[c * Lsz + j];
    }
    g_S1[j] = s1; g_S2[j] = s2; g_S3[j] = s3;
}

// ---------------- adj (corr>0.5) + consistency term -------------------------
__global__ void adjcons_kernel(const float* __restrict__ fe)
{
    __shared__ double red[256];
    const int tid = threadIdx.x;
    double cons = 0.0;
    for (int j = tid; j < Lsz; j += 256) {
        double m = g_S1[j] / (double)Bsz;
        cons += fabs(m - (double)fe[j]);
        if (j < Lsz - 1) {
            double cov = g_S3[j] - g_S1[j] * g_S1[j + 1] / (double)Bsz;
            double v1  = g_S2[j]     - g_S1[j]     * g_S1[j]     / (double)Bsz;
            double v2  = g_S2[j + 1] - g_S1[j + 1] * g_S1[j + 1] / (double)Bsz;
            double den = v1 * v2;
            float a = 0.f;
            if (den > 0.0 && cov / sqrt(den) > 0.5) a = 1.f;
            g_adj[j] = a;
        }
    }
    red[tid] = cons; __syncthreads();
    for (int o = 128; o > 0; o >>= 1) { if (tid < o) red[tid] += red[tid + o]; __syncthreads(); }
    if (tid == 0) g_cons[0] = red[0];
}

// ---------------- per-row mask / top-k / outputs -----------------------------
__global__ void __launch_bounds__(256)
rowmask_kernel(const float* __restrict__ Z, const int* __restrict__ ids,
               float* __restrict__ outG, float* __restrict__ outZ)
{
    __shared__ float zs[Lsz];
    __shared__ float redf[256];
    __shared__ int   redi[256];
    __shared__ unsigned int hist[256];
    __shared__ unsigned int sh_prefix;
    __shared__ int sh_k;
    __shared__ int wsum[8];

    const int r = blockIdx.x, tid = threadIdx.x;
    for (int j = tid; j < Lsz; j += 256) zs[j] = Z[(size_t)r * Lsz + j];
    __syncthreads();

    float ent = 0.f, dif = 0.f;
    int cnt = 0;
    for (int j = tid; j < Lsz; j += 256) {
        float p = zs[j];
        ent += -(p * logf(__fadd_rn(p, 1e-7f)) +
                 (1.f - p) * logf(__fadd_rn(__fsub_rn(1.f, p), 1e-7f)));
        if (j < Lsz - 1) dif += fabsf(__fsub_rn(zs[j + 1], zs[j])) * g_adj[j];
        if (j < Ssz) {
            int tok = ids[(size_t)r * Ssz + j];
            if (p < 0.5f && tok != 0) cnt++;
        }
    }
    redf[tid] = ent; __syncthreads();
    for (int o = 128; o > 0; o >>= 1) { if (tid < o) redf[tid] += redf[tid + o]; __syncthreads(); }
    if (tid == 0) g_rowEnt[r] = redf[0];
    __syncthreads();
    redf[tid] = dif; __syncthreads();
    for (int o = 128; o > 0; o >>= 1) { if (tid < o) redf[tid] += redf[tid + o]; __syncthreads(); }
    if (tid == 0) g_rowDiff[r] = redf[0];
    __syncthreads();
    redi[tid] = cnt; __syncthreads();
    for (int o = 128; o > 0; o >>= 1) { if (tid < o) redi[tid] += redi[tid + o]; __syncthreads(); }
    const int total = redi[0];
    __syncthreads();
    const bool needfix = total > NEEDFIX_THRESH;

    unsigned int tsel = 0;
    int nEqKeep = 0;
    if (needfix) {
        unsigned int prefix = 0, highmask = 0;
        int k = MINTOK;
        for (int pass = 0; pass < 4; pass++) {
            const int shift = 24 - 8 * pass;
            hist[tid] = 0;
            __syncthreads();
            for (int j = tid; j < Ssz; j += 256) {
                unsigned int key = __float_as_uint(zs[j]);
                if ((key & highmask) == prefix)
                    atomicAdd(&hist[(key >> shift) & 0xFFu], 1u);
            }
            __syncthreads();
            if (tid == 0) {
                int cum = 0, b = 255;
                for (; b >= 0; --b) { cum += (int)hist[b]; if (cum >= k) break; }
                sh_k = k - (cum - (int)hist[b]);
                sh_prefix = prefix | ((unsigned int)b << shift);
            }
            __syncthreads();
            prefix = sh_prefix;
            k = sh_k;
            highmask |= 0xFFu << shift;
            __syncthreads();
        }
        tsel = prefix;
        int cg = 0;
        for (int j = tid; j < Ssz; j += 256)
            if (__float_as_uint(zs[j]) > tsel) cg++;
        redi[tid] = cg; __syncthreads();
        for (int o = 128; o > 0; o >>= 1) { if (tid < o) redi[tid] += redi[tid + o]; __syncthreads(); }
        nEqKeep = MINTOK - redi[0];
        __syncthreads();
    }

    int runEq = 0;
    for (int base = 0; base < Ssz; base += 256) {
        const int j = base + tid;
        const float zv = zs[j];
        const int tok = ids[(size_t)r * Ssz + j];
        bool m = (zv < 0.5f) && (tok != 0);
        if (needfix) {
            const unsigned int key = __float_as_uint(zv);
            const int eq = (key == tsel) ? 1 : 0;
            const unsigned int bal = __ballot_sync(0xffffffffu, eq);
            const int lane = tid & 31, w = tid >> 5;
            const int wexcl = __popc(bal & ((1u << lane) - 1u));
            if (lane == 31) wsum[w] = __popc(bal);
            __syncthreads();
            int woff = 0;
            for (int i = 0; i < w; i++) woff += wsum[i];
            const int excl = woff + wexcl;
            const bool keep = (key > tsel) || (eq && (runEq + excl) < nEqKeep);
            if (keep) m = false;
            __syncthreads();
            if (tid == 0) { int t = 0; for (int i = 0; i < 8; i++) t += wsum[i]; redi[0] = t; }
            __syncthreads();
            runEq += redi[0];
        }
        if (j == 0) m = false;
        outG[(size_t)r * Ssz + j] = m ? 0.f : (float)tok;
        outZ[(size_t)r * Ssz + j] = zv;
    }
}

// ---------------- final loss scalar -----------------------------------------
__global__ void finalize_kernel(float* __restrict__ out)
{
    __shared__ double red[256];
    const int tid = threadIdx.x;
    double e = 0, d = 0;
    for (int r = tid; r < Bsz; r += 256) {
        e += (double)g_rowEnt[r];
        d += (double)g_rowDiff[r];
    }
    red[tid] = e; __syncthreads();
    for (int o = 128; o > 0; o >>= 1) { if (tid < o) red[tid] += red[tid + o]; __syncthreads(); }
    const double entSum = red[0];
    __syncthreads();
    red[tid] = d; __syncthreads();
    for (int o = 128; o > 0; o >>= 1) { if (tid < o) red[tid] += red[tid + o]; __syncthreads(); }
    const double difSum = red[0];
    if (tid == 0) {
        double R1 = -0.001 * entSum / ((double)Bsz * (double)Lsz);
        double R2 =  0.001 * difSum / ((double)Bsz * (double)(Lsz - 1));
        double cons = 0.001 * g_cons[0] / (double)Lsz;
        out[(size_t)Bsz * Ssz] = (float)(R1 + R2 + cons);
    }
}

// ---------------- launch ------------------------------------------------------
extern "C" void kernel_launch(void* const* d_in, const int* in_sizes, int n_in,
                              void* d_out, int out_size)
{
    const float* in_g  = (const float*)d_in[0];
    const float* in_b  = (const float*)d_in[1];
    const float* wv    = (const float*)d_in[2];
    const float* bv    = (const float*)d_in[3];
    const float* wo    = (const float*)d_in[4];
    const float* bo    = (const float*)d_in[5];
    const float* w2    = (const float*)d_in[6];
    const float* b2    = (const float*)d_in[7];
    const float* g1    = (const float*)d_in[8];
    const float* be1   = (const float*)d_in[9];
    const float* w4    = (const float*)d_in[10];
    const float* b4    = (const float*)d_in[11];
    const float* g3    = (const float*)d_in[12];
    const float* be3   = (const float*)d_in[13];
    const float* w5    = (const float*)d_in[14];
    const float* b5    = (const float*)d_in[15];
    const float* g4    = (const float*)d_in[16];
    const float* be4   = (const float*)d_in[17];
    const float* w6    = (const float*)d_in[18];
    const float* b6    = (const float*)d_in[19];
    const float* g5    = (const float*)d_in[20];
    const float* be5   = (const float*)d_in[21];
    const float* w7    = (const float*)d_in[22];
    const float* b7    = (const float*)d_in[23];
    const float* g6    = (const float*)d_in[24];
    const float* be6   = (const float*)d_in[25];
    const float* wout  = (const float*)d_in[26];
    const float* bout  = (const float*)d_in[27];
    const float* fe    = (const float*)d_in[28];
    const int*   ids   = (const int*)d_in[29];
    float* out = (float*)d_out;

    float *pA, *pBf, *pC1, *pC2, *pC3, *pD1, *pD2;
    cudaGetSymbolAddress((void**)&pA,  g_A);
    cudaGetSymbolAddress((void**)&pBf, g_Bf);
    cudaGetSymbolAddress((void**)&pC1, g_C1);
    cudaGetSymbolAddress((void**)&pC2, g_C2);
    cudaGetSymbolAddress((void**)&pC3, g_C3);
    cudaGetSymbolAddress((void**)&pD1, g_D1);
    cudaGetSymbolAddress((void**)&pD2, g_D2);

    ln_input_kernel<<<Bsz, 256>>>(ids, in_g, in_b, pA);

    sgemm_nt<<<dim3(Lsz/64, Bsz/64), 256>>>(pA,  wv, bv, pBf, Bsz, Lsz, Lsz);
    sgemm_nt<<<dim3(Lsz/64, Bsz/64), 256>>>(pBf, wo, bo, pA,  Bsz, Lsz, Lsz);

    sgemm_nt<<<dim3(Hsz/64, Bsz/64), 256>>>(pA, w2, b2, pC1, Bsz, Hsz, Lsz);
    ln_gelu_kernel<<<Bsz, 256>>>(pC1, g1, be1, pC1, pC2, Hsz);

    sgemm_nt<<<dim3(Hsz/64, Bsz/64), 256>>>(pC2, w4, b4, pC3, Bsz, Hsz, Hsz);
    ln_gelu_kernel<<<Bsz, 256>>>(pC3, g3, be3, nullptr, pC3, Hsz);

    sgemm_nt<<<dim3(Hsz/64, Bsz/64), 256>>>(pC3, w5, b5, pC1, Bsz, Hsz, Hsz);
    ln_gelu_kernel<<<Bsz, 256>>>(pC1, g4, be4, pC2, pC1, Hsz);

    sgemm_nt<<<dim3((Hsz/2)/64, Bsz/64), 256>>>(pC1, w6, b6, pD1, Bsz, Hsz/2, Hsz);
    ln_gelu_kernel<<<Bsz, 256>>>(pD1, g5, be5, nullptr, pD1, Hsz/2);

    sgemm_nt<<<dim3((Hsz/4)/64, Bsz/64), 256>>>(pD1, w7, b7, pD2, Bsz, Hsz/4, Hsz/2);
    ln_gelu_kernel<<<Bsz, 256>>>(pD2, g6, be6, nullptr, pD2, Hsz/4);

    sgemm_nt<<<dim3(Lsz/64, Bsz/64), 256>>>(pD2, wout, bout, pBf, Bsz, Lsz, Hsz/4);
    sigmoid_kernel<<<(Bsz*Lsz)/256, 256>>>(pBf, pA);

    colstats_kernel<<<dim3(Lsz/256, CCH), 256>>>(pA);
    colcombine_kernel<<<Lsz/256, 256>>>();
    adjcons_kernel<<<1, 256>>>(fe);

    rowmask_kernel<<<Bsz, 256>>>(pA, ids, out, out + (size_t)Bsz * Ssz + 1);

    finalize_kernel<<<1, 256>>>(out);
}

// round 8
// speedup vs baseline: 6.0427x; 1.1419x over previous
#include <cuda_runtime.h>
#include <cuda_bf16.h>
#include <math.h>

// Problem constants
#define Bsz 4096
#define Ssz 1536
#define Lsz 2048
#define Hsz 1024
#define MINTOK 460                     // int(0.3*1536)
#define NEEDFIX_THRESH (Ssz - MINTOK)  // 1076

// ---------------- scratch (device globals; no allocations allowed) ----------
__device__ float g_A [(size_t)Bsz * Lsz];
__device__ float g_Bf[(size_t)Bsz * Lsz];
__device__ float g_C1[(size_t)Bsz * Hsz];
__device__ float g_C2[(size_t)Bsz * Hsz];
__device__ float g_C3[(size_t)Bsz * Hsz];
__device__ float g_D1[(size_t)Bsz * (Hsz/2)];
__device__ float g_D2[(size_t)Bsz * (Hsz/4)];

#define CCH 16
__device__ double g_p1[CCH * Lsz];
__device__ double g_p2[CCH * Lsz];
__device__ double g_p3[CCH * Lsz];
__device__ double g_S1[Lsz], g_S2[Lsz], g_S3[Lsz];
__device__ float  g_adj[Lsz];
__device__ float  g_rowEnt[Bsz], g_rowDiff[Bsz];
__device__ double g_cons[1];

// ---- f32x2 packed helpers (PTX-only; each half is an independent IEEE op) --
__device__ __forceinline__ unsigned long long pk2(float lo, float hi) {
    unsigned long long r;
    asm("mov.b64 %0, {%1, %2};" : "=l"(r) : "f"(lo), "f"(hi));
    return r;
}
__device__ __forceinline__ void upk2(unsigned long long v, float& lo, float& hi) {
    asm("mov.b64 {%0, %1}, %2;" : "=f"(lo), "=f"(hi) : "l"(v));
}
__device__ __forceinline__ unsigned long long fma2(unsigned long long a,
                                                   unsigned long long b,
                                                   unsigned long long c) {
    unsigned long long d;
    asm("fma.rn.f32x2 %0, %1, %2, %3;" : "=l"(d) : "l"(a), "l"(b), "l"(c));
    return d;
}

union F4U2 { float4 f; struct { unsigned long long lo, hi; } u; };

// ---------------- GEMM: C[M,N] = A[M,K] @ W[N,K]^T + bias[N] ----------------
// Numerics contract (frozen; outputs bitwise-identical to rounds 6/7): per
// output, fp32 FFMA over each ascending 64-k chunk; chunks folded ascending
// into a Kahan (ksum, kcmp) fp32 pair; (ksum+kcmp)+bias at the end. f32x2
// packs two M-adjacent outputs per instruction — identical IEEE arithmetic.
// Perf: 128x64 block tile, 8x4/thread, 256 threads, BK=32 double-buffered
// stages + register prefetch, FFMA2 inner loop.
__global__ void __launch_bounds__(256)
sgemm_nt(const float* __restrict__ A, const float* __restrict__ W,
         const float* __restrict__ bias, float* __restrict__ C,
         int M, int N, int K)
{
    constexpr int BK = 32;
    __shared__ float As[2][BK][64 + 4];   // [k][row] rows 0..127 -> two halves
    __shared__ float As2[2][BK][64 + 4];  // rows 64..127
    __shared__ float Bs[2][BK][64 + 4];
    const int tid = threadIdx.x;
    const int bm = blockIdx.y * 128;
    const int bn = blockIdx.x * 64;
    const int tr = (tid >> 4) << 3;     // 0..120 step 8 (C row offset)
    const int tc = (tid & 15) << 2;     // 0..60 step 4 (C col offset)

    // staging: A 128x32 -> 16 floats/thread; B 64x32 -> 8 floats/thread
    const int arow = tid & 127;
    const int ak   = (tid >> 7) << 4;   // 0 or 16
    const int brow = tid & 63;
    const int bk   = (tid >> 6) << 3;   // 0,8,16,24

    const float* Ap = A + (size_t)(bm + arow) * K + ak;
    const float* Wp = W + (size_t)(bn + brow) * K + bk;

    // A smem split: rows 0..63 in As, rows 64..127 in As2 (same [k][row] form)
    float* const aDst0 = (arow < 64) ? &As [0][0][0] : &As2[0][0][0];
    float* const aDst1 = (arow < 64) ? &As [1][0][0] : &As2[1][0][0];
    const int arl = arow & 63;

    unsigned long long facc2[4][4];     // M-pairs (tr+2mi, tr+2mi+1) x 4 N
    float ksum[8][4], kcmp[8][4];
#pragma unroll
    for (int i = 0; i < 8; i++)
#pragma unroll
        for (int j = 0; j < 4; j++) { ksum[i][j] = 0.f; kcmp[i][j] = 0.f; }
#pragma unroll
    for (int mi = 0; mi < 4; mi++)
#pragma unroll
        for (int j = 0; j < 4; j++) facc2[mi][j] = 0ull;

    const int nch = K / BK;   // 32-k stages; Kahan fold every 2 stages (64 k)

    float4 aq[4], bq[2];
#pragma unroll
    for (int q = 0; q < 4; q++) aq[q] = *(const float4*)(Ap + q * 4);
#pragma unroll
    for (int q = 0; q < 2; q++) bq[q] = *(const float4*)(Wp + q * 4);

    {
        float* ad = aDst0;
#pragma unroll
        for (int q = 0; q < 4; q++) {
            const int kk = ak + q * 4;
            ad[(kk + 0) * 68 + arl] = aq[q].x; ad[(kk + 1) * 68 + arl] = aq[q].y;
            ad[(kk + 2) * 68 + arl] = aq[q].z; ad[(kk + 3) * 68 + arl] = aq[q].w;
        }
#pragma unroll
        for (int q = 0; q < 2; q++) {
            const int kk = bk + q * 4;
            Bs[0][kk + 0][brow] = bq[q].x; Bs[0][kk + 1][brow] = bq[q].y;
            Bs[0][kk + 2][brow] = bq[q].z; Bs[0][kk + 3][brow] = bq[q].w;
        }
    }
    __syncthreads();

    const bool lowHalf = (tr < 64);
    const int trl = tr & 63;

    for (int c = 0; c < nch; c++) {
        const int buf = c & 1;
        const bool more = (c + 1 < nch);
        if (more) {
            const int k0 = (c + 1) * BK;
#pragma unroll
            for (int q = 0; q < 4; q++) aq[q] = *(const float4*)(Ap + k0 + q * 4);
#pragma unroll
            for (int q = 0; q < 2; q++) bq[q] = *(const float4*)(Wp + k0 + q * 4);
        }

        const float* aSrcA = (lowHalf ? &As[buf][0][0] : &As2[buf][0][0]) + trl;
        const float* bSrc  = &Bs[buf][0][0] + tc;

#pragma unroll
        for (int k = 0; k < BK; k++) {
            F4U2 a0, a1;
            a0.f = *(const float4*)(aSrcA + k * 68);
            a1.f = *(const float4*)(aSrcA + k * 68 + 4);
            const float4 bv = *(const float4*)(bSrc + k * 68);
            const unsigned long long bb0 = pk2(bv.x, bv.x);
            const unsigned long long bb1 = pk2(bv.y, bv.y);
            const unsigned long long bb2 = pk2(bv.z, bv.z);
            const unsigned long long bb3 = pk2(bv.w, bv.w);
            facc2[0][0] = fma2(a0.u.lo, bb0, facc2[0][0]);
            facc2[0][1] = fma2(a0.u.lo, bb1, facc2[0][1]);
            facc2[0][2] = fma2(a0.u.lo, bb2, facc2[0][2]);
            facc2[0][3] = fma2(a0.u.lo, bb3, facc2[0][3]);
            facc2[1][0] = fma2(a0.u.hi, bb0, facc2[1][0]);
            facc2[1][1] = fma2(a0.u.hi, bb1, facc2[1][1]);
            facc2[1][2] = fma2(a0.u.hi, bb2, facc2[1][2]);
            facc2[1][3] = fma2(a0.u.hi, bb3, facc2[1][3]);
            facc2[2][0] = fma2(a1.u.lo, bb0, facc2[2][0]);
            facc2[2][1] = fma2(a1.u.lo, bb1, facc2[2][1]);
            facc2[2][2] = fma2(a1.u.lo, bb2, facc2[2][2]);
            facc2[2][3] = fma2(a1.u.lo, bb3, facc2[2][3]);
            facc2[3][0] = fma2(a1.u.hi, bb0, facc2[3][0]);
            facc2[3][1] = fma2(a1.u.hi, bb1, facc2[3][1]);
            facc2[3][2] = fma2(a1.u.hi, bb2, facc2[3][2]);
            facc2[3][3] = fma2(a1.u.hi, bb3, facc2[3][3]);
        }

        if ((c & 1) == 1) {
            // Kahan fold of the completed 64-k chunk into (ksum, kcmp)
#pragma unroll
            for (int mi = 0; mi < 4; mi++)
#pragma unroll
                for (int j = 0; j < 4; j++) {
                    float flo, fhi;
                    upk2(facc2[mi][j], flo, fhi);
                    {
                        const int i = 2 * mi;
                        const float t = __fadd_rn(ksum[i][j], flo);
                        const float e = __fadd_rn(__fsub_rn(ksum[i][j], t), flo);
                        kcmp[i][j] = __fadd_rn(kcmp[i][j], e);
                        ksum[i][j] = t;
                    }
                    {
                        const int i = 2 * mi + 1;
                        const float t = __fadd_rn(ksum[i][j], fhi);
                        const float e = __fadd_rn(__fsub_rn(ksum[i][j], t), fhi);
                        kcmp[i][j] = __fadd_rn(kcmp[i][j], e);
                        ksum[i][j] = t;
                    }
                    facc2[mi][j] = 0ull;
                }
        }

        if (more) {
            __syncthreads();
            const int nb = buf ^ 1;
            float* ad = nb ? aDst1 : aDst0;
#pragma unroll
            for (int q = 0; q < 4; q++) {
                const int kk = ak + q * 4;
                ad[(kk + 0) * 68 + arl] = aq[q].x; ad[(kk + 1) * 68 + arl] = aq[q].y;
                ad[(kk + 2) * 68 + arl] = aq[q].z; ad[(kk + 3) * 68 + arl] = aq[q].w;
            }
#pragma unroll
            for (int q = 0; q < 2; q++) {
                const int kk = bk + q * 4;
                Bs[nb][kk + 0][brow] = bq[q].x; Bs[nb][kk + 1][brow] = bq[q].y;
                Bs[nb][kk + 2][brow] = bq[q].z; Bs[nb][kk + 3][brow] = bq[q].w;
            }
            __syncthreads();
        }
    }

    float bj[4];
#pragma unroll
    for (int j = 0; j < 4; j++) bj[j] = bias[bn + tc + j];
#pragma unroll
    for (int i = 0; i < 8; i++) {
        float* Cp = C + (size_t)(bm + tr + i) * N + bn + tc;
        float4 v;
        v.x = __fadd_rn(__fadd_rn(ksum[i][0], kcmp[i][0]), bj[0]);
        v.y = __fadd_rn(__fadd_rn(ksum[i][1], kcmp[i][1]), bj[1]);
        v.z = __fadd_rn(__fadd_rn(ksum[i][2], kcmp[i][2]), bj[2]);
        v.w = __fadd_rn(__fadd_rn(ksum[i][3], kcmp[i][3]), bj[3]);
        *(float4*)Cp = v;
    }
}

// ---------------- LN of padded int input -> X0 (double-precise stats) -------
__global__ void ln_input_kernel(const int* __restrict__ ids,
                                const float* __restrict__ gam,
                                const float* __restrict__ bet,
                                float* __restrict__ out)
{
    __shared__ float s[Lsz];
    __shared__ double red[256];
    const int r = blockIdx.x, tid = threadIdx.x;
    for (int j = tid; j < Lsz; j += 256)
        s[j] = (j < Ssz) ? (float)ids[(size_t)r * Ssz + j] : 0.f;
    __syncthreads();
    double p = 0.0;
    for (int j = tid; j < Lsz; j += 256) p += (double)s[j];
    red[tid] = p; __syncthreads();
    for (int o = 128; o > 0; o >>= 1) { if (tid < o) red[tid] += red[tid + o]; __syncthreads(); }
    const double mean = red[0] / (double)Lsz;
    const float  mf   = (float)mean;
    __syncthreads();
    double v = 0.0;
    for (int j = tid; j < Lsz; j += 256) { double d = (double)s[j] - mean; v += d * d; }
    red[tid] = v; __syncthreads();
    for (int o = 128; o > 0; o >>= 1) { if (tid < o) red[tid] += red[tid + o]; __syncthreads(); }
    const float vf  = (float)(red[0] / (double)Lsz);
    const float arg = __fadd_rn(vf, 1e-5f);
    const float rs  = (float)(1.0 / sqrt((double)arg));
    for (int j = tid; j < Lsz; j += 256) {
        float t = __fmul_rn(__fmul_rn(__fsub_rn(s[j], mf), rs), gam[j]);
        out[(size_t)r * Lsz + j] = __fadd_rn(t, bet[j]);
    }
}

// ---------------- LN + exact GELU (+ optional residual), per row ------------
__global__ void ln_gelu_kernel(const float* __restrict__ in,
                               const float* __restrict__ gam,
                               const float* __restrict__ bet,
                               const float* __restrict__ res,
                               float* __restrict__ out, int n)
{
    __shared__ float s[Lsz];
    __shared__ double red[256];
    const int r = blockIdx.x, tid = threadIdx.x;
    for (int j = tid; j < n; j += 256) s[j] = in[(size_t)r * n + j];
    __syncthreads();
    double p = 0.0;
    for (int j = tid; j < n; j += 256) p += (double)s[j];
    red[tid] = p; __syncthreads();
    for (int o = 128; o > 0; o >>= 1) { if (tid < o) red[tid] += red[tid + o]; __syncthreads(); }
    const double mean = red[0] / (double)n;
    const float  mf   = (float)mean;
    __syncthreads();
    double v = 0.0;
    for (int j = tid; j < n; j += 256) { double d = (double)s[j] - mean; v += d * d; }
    red[tid] = v; __syncthreads();
    for (int o = 128; o > 0; o >>= 1) { if (tid < o) red[tid] += red[tid + o]; __syncthreads(); }
    const float vf  = (float)(red[0] / (double)n);
    const float arg = __fadd_rn(vf, 1e-5f);
    const float rs  = (float)(1.0 / sqrt((double)arg));
    for (int j = tid; j < n; j += 256) {
        float x = __fadd_rn(__fmul_rn(__fmul_rn(__fsub_rn(s[j], mf), rs), gam[j]), bet[j]);
        float u = __fmul_rn(x, 0.70710678118654752f);
        float e = erff(u);
        float ge = __fmul_rn(__fmul_rn(x, __fadd_rn(e, 1.f)), 0.5f);
        float o = res ? __fadd_rn(ge, res[(size_t)r * n + j]) : ge;
        out[(size_t)r * n + j] = o;
    }
}

// ---------------- mu -> z = sigmoid(clip(mu,-5,5)), exact -------------------
__global__ void sigmoid_kernel(const float* __restrict__ mu, float* __restrict__ z)
{
    size_t i = (size_t)blockIdx.x * 256 + threadIdx.x;
    if (i < (size_t)Bsz * Lsz) {
        float m = mu[i];
        m = fminf(5.f, fmaxf(-5.f, m));
        z[i] = (float)(1.0 / (1.0 + exp(-(double)m)));
    }
}

// ---------------- column stats ----------------------------------------------
__global__ void colstats_kernel(const float* __restrict__ Z)
{
    const int j  = blockIdx.x * 256 + threadIdx.x;
    const int ch = blockIdx.y;
    const int r0 = ch * (Bsz / CCH);
    const bool hasN = (j < Lsz - 1);
    double s1 = 0, s2 = 0, s3 = 0;
    for (int r = r0; r < r0 + (Bsz / CCH); ++r) {
        float z  = Z[(size_t)r * Lsz + j];
        float zn = hasN ? Z[(size_t)r * Lsz + j + 1] : 0.f;
        s1 += (double)z;
        s2 += (double)z * (double)z;
        s3 += (double)z * (double)zn;
    }
    g_p1[ch * Lsz + j] = s1;
    g_p2[ch * Lsz + j] = s2;
    g_p3[ch * Lsz + j] = s3;
}

__global__ void colcombine_kernel()
{
    const int j = blockIdx.x * 256 + threadIdx.x;
    double s1 = 0, s2 = 0, s3 = 0;
    for (int c = 0; c < CCH; c++) {
        s1 += g_p1[c * Lsz + j];
        s2 += g_p2[c * Lsz + j];
        s3 += g_p3[c * Lsz + j];
    }
    g_S1[j] = s1; g_S2[j] = s2; g_S3[j] = s3;
}

// ---------------- adj (corr>0.5) + consistency term -------------------------
__global__ void adjcons_kernel(const float* __restrict__ fe)
{
    __shared__ double red[256];
    const int tid = threadIdx.x;
    double cons = 0.0;
    for (int j = tid; j < Lsz; j += 256) {
        double m = g_S1[j] / (double)Bsz;
        cons += fabs(m - (double)fe[j]);
        if (j < Lsz - 1) {
            double cov = g_S3[j] - g_S1[j] * g_S1[j + 1] / (double)Bsz;
            double v1  = g_S2[j]     - g_S1[j]     * g_S1[j]     / (double)Bsz;
            double v2  = g_S2[j + 1] - g_S1[j + 1] * g_S1[j + 1] / (double)Bsz;
            double den = v1 * v2;
            float a = 0.f;
            if (den > 0.0 && cov / sqrt(den) > 0.5) a = 1.f;
            g_adj[j] = a;
        }
    }
    red[tid] = cons; __syncthreads();
    for (int o = 128; o > 0; o >>= 1) { if (tid < o) red[tid] += red[tid + o]; __syncthreads(); }
    if (tid == 0) g_cons[0] = red[0];
}

// ---------------- per-row mask / top-k / outputs -----------------------------
__global__ void __launch_bounds__(256)
rowmask_kernel(const float* __restrict__ Z, const int* __restrict__ ids,
               float* __restrict__ outG, float* __restrict__ outZ)
{
    __shared__ float zs[Lsz];
    __shared__ float redf[256];
    __shared__ int   redi[256];
    __shared__ unsigned int hist[256];
    __shared__ unsigned int sh_prefix;
    __shared__ int sh_k;
    __shared__ int wsum[8];

    const int r = blockIdx.x, tid = threadIdx.x;
    for (int j = tid; j < Lsz; j += 256) zs[j] = Z[(size_t)r * Lsz + j];
    __syncthreads();

    float ent = 0.f, dif = 0.f;
    int cnt = 0;
    for (int j = tid; j < Lsz; j += 256) {
        float p = zs[j];
        ent += -(p * logf(__fadd_rn(p, 1e-7f)) +
                 (1.f - p) * logf(__fadd_rn(__fsub_rn(1.f, p), 1e-7f)));
        if (j < Lsz - 1) dif += fabsf(__fsub_rn(zs[j + 1], zs[j])) * g_adj[j];
        if (j < Ssz) {
            int tok = ids[(size_t)r * Ssz + j];
            if (p < 0.5f && tok != 0) cnt++;
        }
    }
    redf[tid] = ent; __syncthreads();
    for (int o = 128; o > 0; o >>= 1) { if (tid < o) redf[tid] += redf[tid + o]; __syncthreads(); }
    if (tid == 0) g_rowEnt[r] = redf[0];
    __syncthreads();
    redf[tid] = dif; __syncthreads();
    for (int o = 128; o > 0; o >>= 1) { if (tid < o) redf[tid] += redf[tid + o]; __syncthreads(); }
    if (tid == 0) g_rowDiff[r] = redf[0];
    __syncthreads();
    redi[tid] = cnt; __syncthreads();
    for (int o = 128; o > 0; o >>= 1) { if (tid < o) redi[tid] += redi[tid + o]; __syncthreads(); }
    const int total = redi[0];
    __syncthreads();
    const bool needfix = total > NEEDFIX_THRESH;

    unsigned int tsel = 0;
    int nEqKeep = 0;
    if (needfix) {
        unsigned int prefix = 0, highmask = 0;
        int k = MINTOK;
        for (int pass = 0; pass < 4; pass++) {
            const int shift = 24 - 8 * pass;
            hist[tid] = 0;
            __syncthreads();
            for (int j = tid; j < Ssz; j += 256) {
                unsigned int key = __float_as_uint(zs[j]);
                if ((key & highmask) == prefix)
                    atomicAdd(&hist[(key >> shift) & 0xFFu], 1u);
            }
            __syncthreads();
            if (tid == 0) {
                int cum = 0, b = 255;
                for (; b >= 0; --b) { cum += (int)hist[b]; if (cum >= k) break; }
                sh_k = k - (cum - (int)hist[b]);
                sh_prefix = prefix | ((unsigned int)b << shift);
            }
            __syncthreads();
            prefix = sh_prefix;
            k = sh_k;
            highmask |= 0xFFu << shift;
            __syncthreads();
        }
        tsel = prefix;
        int cg = 0;
        for (int j = tid; j < Ssz; j += 256)
            if (__float_as_uint(zs[j]) > tsel) cg++;
        redi[tid] = cg; __syncthreads();
        for (int o = 128; o > 0; o >>= 1) { if (tid < o) redi[tid] += redi[tid + o]; __syncthreads(); }
        nEqKeep = MINTOK - redi[0];
        __syncthreads();
    }

    int runEq = 0;
    for (int base = 0; base < Ssz; base += 256) {
        const int j = base + tid;
        const float zv = zs[j];
        const int tok = ids[(size_t)r * Ssz + j];
        bool m = (zv < 0.5f) && (tok != 0);
        if (needfix) {
            const unsigned int key = __float_as_uint(zv);
            const int eq = (key == tsel) ? 1 : 0;
            const unsigned int bal = __ballot_sync(0xffffffffu, eq);
            const int lane = tid & 31, w = tid >> 5;
            const int wexcl = __popc(bal & ((1u << lane) - 1u));
            if (lane == 31) wsum[w] = __popc(bal);
            __syncthreads();
            int woff = 0;
            for (int i = 0; i < w; i++) woff += wsum[i];
            const int excl = woff + wexcl;
            const bool keep = (key > tsel) || (eq && (runEq + excl) < nEqKeep);
            if (keep) m = false;
            __syncthreads();
            if (tid == 0) { int t = 0; for (int i = 0; i < 8; i++) t += wsum[i]; redi[0] = t; }
            __syncthreads();
            runEq += redi[0];
        }
        if (j == 0) m = false;
        outG[(size_t)r * Ssz + j] = m ? 0.f : (float)tok;
        outZ[(size_t)r * Ssz + j] = zv;
    }
}

// ---------------- final loss scalar -----------------------------------------
__global__ void finalize_kernel(float* __restrict__ out)
{
    __shared__ double red[256];
    const int tid = threadIdx.x;
    double e = 0, d = 0;
    for (int r = tid; r < Bsz; r += 256) {
        e += (double)g_rowEnt[r];
        d += (double)g_rowDiff[r];
    }
    red[tid] = e; __syncthreads();
    for (int o = 128; o > 0; o >>= 1) { if (tid < o) red[tid] += red[tid + o]; __syncthreads(); }
    const double entSum = red[0];
    __syncthreads();
    red[tid] = d; __syncthreads();
    for (int o = 128; o > 0; o >>= 1) { if (tid < o) red[tid] += red[tid + o]; __syncthreads(); }
    const double difSum = red[0];
    if (tid == 0) {
        double R1 = -0.001 * entSum / ((double)Bsz * (double)Lsz);
        double R2 =  0.001 * difSum / ((double)Bsz * (double)(Lsz - 1));
        double cons = 0.001 * g_cons[0] / (double)Lsz;
        out[(size_t)Bsz * Ssz] = (float)(R1 + R2 + cons);
    }
}

// ---------------- launch ------------------------------------------------------
extern "C" void kernel_launch(void* const* d_in, const int* in_sizes, int n_in,
                              void* d_out, int out_size)
{
    const float* in_g  = (const float*)d_in[0];
    const float* in_b  = (const float*)d_in[1];
    const float* wv    = (const float*)d_in[2];
    const float* bv    = (const float*)d_in[3];
    const float* wo    = (const float*)d_in[4];
    const float* bo    = (const float*)d_in[5];
    const float* w2    = (const float*)d_in[6];
    const float* b2    = (const float*)d_in[7];
    const float* g1    = (const float*)d_in[8];
    const float* be1   = (const float*)d_in[9];
    const float* w4    = (const float*)d_in[10];
    const float* b4    = (const float*)d_in[11];
    const float* g3    = (const float*)d_in[12];
    const float* be3   = (const float*)d_in[13];
    const float* w5    = (const float*)d_in[14];
    const float* b5    = (const float*)d_in[15];
    const float* g4    = (const float*)d_in[16];
    const float* be4   = (const float*)d_in[17];
    const float* w6    = (const float*)d_in[18];
    const float* b6    = (const float*)d_in[19];
    const float* g5    = (const float*)d_in[20];
    const float* be5   = (const float*)d_in[21];
    const float* w7    = (const float*)d_in[22];
    const float* b7    = (const float*)d_in[23];
    const float* g6    = (const float*)d_in[24];
    const float* be6   = (const float*)d_in[25];
    const float* wout  = (const float*)d_in[26];
    const float* bout  = (const float*)d_in[27];
    const float* fe    = (const float*)d_in[28];
    const int*   ids   = (const int*)d_in[29];
    float* out = (float*)d_out;

    float *pA, *pBf, *pC1, *pC2, *pC3, *pD1, *pD2;
    cudaGetSymbolAddress((void**)&pA,  g_A);
    cudaGetSymbolAddress((void**)&pBf, g_Bf);
    cudaGetSymbolAddress((void**)&pC1, g_C1);
    cudaGetSymbolAddress((void**)&pC2, g_C2);
    cudaGetSymbolAddress((void**)&pC3, g_C3);
    cudaGetSymbolAddress((void**)&pD1, g_D1);
    cudaGetSymbolAddress((void**)&pD2, g_D2);

    ln_input_kernel<<<Bsz, 256>>>(ids, in_g, in_b, pA);

    sgemm_nt<<<dim3(Lsz/64, Bsz/128), 256>>>(pA,  wv, bv, pBf, Bsz, Lsz, Lsz);
    sgemm_nt<<<dim3(Lsz/64, Bsz/128), 256>>>(pBf, wo, bo, pA,  Bsz, Lsz, Lsz);

    sgemm_nt<<<dim3(Hsz/64, Bsz/128), 256>>>(pA, w2, b2, pC1, Bsz, Hsz, Lsz);
    ln_gelu_kernel<<<Bsz, 256>>>(pC1, g1, be1, pC1, pC2, Hsz);

    sgemm_nt<<<dim3(Hsz/64, Bsz/128), 256>>>(pC2, w4, b4, pC3, Bsz, Hsz, Hsz);
    ln_gelu_kernel<<<Bsz, 256>>>(pC3, g3, be3, nullptr, pC3, Hsz);

    sgemm_nt<<<dim3(Hsz/64, Bsz/128), 256>>>(pC3, w5, b5, pC1, Bsz, Hsz, Hsz);
    ln_gelu_kernel<<<Bsz, 256>>>(pC1, g4, be4, pC2, pC1, Hsz);

    sgemm_nt<<<dim3((Hsz/2)/64, Bsz/128), 256>>>(pC1, w6, b6, pD1, Bsz, Hsz/2, Hsz);
    ln_gelu_kernel<<<Bsz, 256>>>(pD1, g5, be5, nullptr, pD1, Hsz/2);

    sgemm_nt<<<dim3((Hsz/4)/64, Bsz/128), 256>>>(pD1, w7, b7, pD2, Bsz, Hsz/4, Hsz/2);
    ln_gelu_kernel<<<Bsz, 256>>>(pD2, g6, be6, nullptr, pD2, Hsz/4);

    sgemm_nt<<<dim3(Lsz/64, Bsz/128), 256>>>(pD2, wout, bout, pBf, Bsz, Lsz, Hsz/4);
    sigmoid_kernel<<<(Bsz*Lsz)/256, 256>>>(pBf, pA);

    colstats_kernel<<<dim3(Lsz/256, CCH), 256>>>(pA);
    colcombine_kernel<<<Lsz/256, 256>>>();
    adjcons_kernel<<<1, 256>>>(fe);

    rowmask_kernel<<<Bsz, 256>>>(pA, ids, out, out + (size_t)Bsz * Ssz + 1);

    finalize_kernel<<<1, 256>>>(out);
}